// round 1
// baseline (speedup 1.0000x reference)
#include <cuda_runtime.h>
#include <cuda_bf16.h>
#include <cstdint>

#define NTOK 2560
#define EDIM 512
#define NHEAD 8
#define HDIM 64
#define FFD 2048
#define VOC 32000
#define SEQ 80
#define NLAYER 4

// ---------------- device scratch (no allocations allowed) ----------------
__device__ float g_x[NTOK * EDIM];
__device__ float g_qkv[NTOK * 3 * EDIM];
__device__ float g_t512[NTOK * EDIM];
__device__ float g_h1[NTOK * FFD];
__device__ float g_c[EDIM];
__device__ __nv_bfloat16 g_ahi[NTOK * FFD];
__device__ __nv_bfloat16 g_alo[NTOK * FFD];
__device__ __nv_bfloat16 g_bhi[VOC * EDIM];
__device__ __nv_bfloat16 g_blo[VOC * EDIM];

// ---------------- mma helpers ----------------
__device__ __forceinline__ void ldsm4(uint32_t r[4], const __nv_bfloat16* p) {
    uint32_t a = (uint32_t)__cvta_generic_to_shared(p);
    asm volatile("ldmatrix.sync.aligned.m8n8.x4.shared.b16 {%0,%1,%2,%3},[%4];\n"
                 : "=r"(r[0]), "=r"(r[1]), "=r"(r[2]), "=r"(r[3]) : "r"(a));
}
__device__ __forceinline__ void mma16816(float d[4], const uint32_t a[4], const uint32_t b[2]) {
    asm volatile(
        "mma.sync.aligned.m16n8k16.row.col.f32.bf16.bf16.f32 "
        "{%0,%1,%2,%3},{%4,%5,%6,%7},{%8,%9},{%0,%1,%2,%3};\n"
        : "+f"(d[0]), "+f"(d[1]), "+f"(d[2]), "+f"(d[3])
        : "r"(a[0]), "r"(a[1]), "r"(a[2]), "r"(a[3]), "r"(b[0]), "r"(b[1]));
}

// C[M,N] = A[M,K] * B[N,K]^T + bias, with A,B given as bf16 (hi,lo) splits.
// 3 passes: hi*hi + hi*lo + lo*hi  (error ~2^-16 relative).
// Requires M%128==0, N%128==0, K%32==0 (true for all call sites).
__global__ __launch_bounds__(256) void gemm3_kernel(
    const __nv_bfloat16* __restrict__ Ahi, const __nv_bfloat16* __restrict__ Alo,
    const __nv_bfloat16* __restrict__ Bhi, const __nv_bfloat16* __restrict__ Blo,
    const float* __restrict__ bias, float* __restrict__ C,
    int M, int N, int K, int dorelu)
{
    __shared__ __nv_bfloat16 sA[2][128 * 40];
    __shared__ __nv_bfloat16 sB[2][128 * 40];
    const int bn = blockIdx.x * 128, bm = blockIdx.y * 128;
    const int tid = threadIdx.x, lane = tid & 31, warp = tid >> 5;
    const int wm = (warp & 1) * 64, wn = (warp >> 1) * 32;

    float acc[4][4][4];
#pragma unroll
    for (int a = 0; a < 4; a++)
#pragma unroll
        for (int b = 0; b < 4; b++)
#pragma unroll
            for (int c = 0; c < 4; c++) acc[a][b][c] = 0.f;

    for (int k0 = 0; k0 < K; k0 += 32) {
#pragma unroll
        for (int i = tid; i < 512; i += 256) {
            int r = i >> 2, c8 = (i & 3) * 8;
            size_t ga = (size_t)(bm + r) * K + k0 + c8;
            size_t gb = (size_t)(bn + r) * K + k0 + c8;
            *(float4*)&sA[0][r * 40 + c8] = *(const float4*)&Ahi[ga];
            *(float4*)&sA[1][r * 40 + c8] = *(const float4*)&Alo[ga];
            *(float4*)&sB[0][r * 40 + c8] = *(const float4*)&Bhi[gb];
            *(float4*)&sB[1][r * 40 + c8] = *(const float4*)&Blo[gb];
        }
        __syncthreads();
#pragma unroll
        for (int ks = 0; ks < 2; ks++) {
            int kc = ks * 16;
            uint32_t af[2][4][4];
#pragma unroll
            for (int p = 0; p < 2; p++)
#pragma unroll
                for (int mt = 0; mt < 4; mt++)
                    ldsm4(af[p][mt],
                          &sA[p][(wm + mt * 16 + (lane & 15)) * 40 + kc + (lane >> 4) * 8]);
            uint32_t bf[2][4][2];
#pragma unroll
            for (int p = 0; p < 2; p++)
#pragma unroll
                for (int nt = 0; nt < 4; nt += 2) {
                    int lrow = lane & 7, seg = lane >> 3;
                    uint32_t tmp[4];
                    ldsm4(tmp, &sB[p][(wn + (nt + (seg >> 1)) * 8 + lrow) * 40 + kc + (seg & 1) * 8]);
                    bf[p][nt][0] = tmp[0]; bf[p][nt][1] = tmp[1];
                    bf[p][nt + 1][0] = tmp[2]; bf[p][nt + 1][1] = tmp[3];
                }
#pragma unroll
            for (int mt = 0; mt < 4; mt++)
#pragma unroll
                for (int nt = 0; nt < 4; nt++) {
                    mma16816(acc[mt][nt], af[0][mt], bf[0][nt]);  // hi*hi
                    mma16816(acc[mt][nt], af[0][mt], bf[1][nt]);  // hi*lo
                    mma16816(acc[mt][nt], af[1][mt], bf[0][nt]);  // lo*hi
                }
        }
        __syncthreads();
    }
#pragma unroll
    for (int mt = 0; mt < 4; mt++) {
#pragma unroll
        for (int nt = 0; nt < 4; nt++) {
            int row = bm + wm + mt * 16 + (lane >> 2);
            int col = bn + wn + nt * 8 + (lane & 3) * 2;
            float b0 = bias[col], b1 = bias[col + 1];
            float v0 = acc[mt][nt][0] + b0, v1 = acc[mt][nt][1] + b1;
            float v2 = acc[mt][nt][2] + b0, v3 = acc[mt][nt][3] + b1;
            if (dorelu) {
                v0 = fmaxf(v0, 0.f); v1 = fmaxf(v1, 0.f);
                v2 = fmaxf(v2, 0.f); v3 = fmaxf(v3, 0.f);
            }
            *(float2*)&C[(size_t)row * N + col] = make_float2(v0, v1);
            *(float2*)&C[(size_t)(row + 8) * N + col] = make_float2(v2, v3);
        }
    }
}

// ---------------- fp32 -> bf16 hi/lo split (n4 = count/4) ----------------
__global__ void split_kernel(const float* __restrict__ s, __nv_bfloat16* __restrict__ hi,
                             __nv_bfloat16* __restrict__ lo, int n4)
{
    int i = blockIdx.x * blockDim.x + threadIdx.x;
    if (i >= n4) return;
    float4 v = ((const float4*)s)[i];
    __nv_bfloat16 h0 = __float2bfloat16(v.x), h1 = __float2bfloat16(v.y);
    __nv_bfloat16 h2 = __float2bfloat16(v.z), h3 = __float2bfloat16(v.w);
    ((__nv_bfloat162*)hi)[2 * i]     = __halves2bfloat162(h0, h1);
    ((__nv_bfloat162*)hi)[2 * i + 1] = __halves2bfloat162(h2, h3);
    ((__nv_bfloat162*)lo)[2 * i] = __halves2bfloat162(
        __float2bfloat16(v.x - __bfloat162float(h0)),
        __float2bfloat16(v.y - __bfloat162float(h1)));
    ((__nv_bfloat162*)lo)[2 * i + 1] = __halves2bfloat162(
        __float2bfloat16(v.z - __bfloat162float(h2)),
        __float2bfloat16(v.w - __bfloat162float(h3)));
}

// ---------------- embedding gather: x = W_in[:,tok] + b_in + pos ----------------
__global__ __launch_bounds__(256) void embed_kernel(
    const int* __restrict__ caps, const float* __restrict__ Win,
    const float* __restrict__ bin, const float* __restrict__ pos, float* __restrict__ x)
{
    int n = blockIdx.x;
    int tok = caps[n];
    int l = n % SEQ;
#pragma unroll
    for (int e = threadIdx.x; e < EDIM; e += 256)
        x[(size_t)n * EDIM + e] = Win[(size_t)e * VOC + tok] + bin[e] + pos[l * EDIM + e];
}

// ---------------- causal self-attention, fp32, one block per (b,h) ----------------
__global__ __launch_bounds__(256) void attn_kernel(const float* __restrict__ qkv,
                                                   float* __restrict__ out)
{
    int b = blockIdx.x >> 3, h = blockIdx.x & 7;
    __shared__ float Kt[80 * 65];  // padded: conflict-free strided row access
    __shared__ float Vs[80 * 64];
    __shared__ float pr[8 * 80];
    const float* base = qkv + (size_t)b * SEQ * 3 * EDIM;
    for (int i = threadIdx.x; i < 80 * 64; i += 256) {
        int t = i >> 6, d = i & 63;
        Kt[t * 65 + d] = base[t * 1536 + 512 + h * 64 + d];
        Vs[i]          = base[t * 1536 + 1024 + h * 64 + d];
    }
    __syncthreads();
    int warp = threadIdx.x >> 5, lane = threadIdx.x & 31;
    for (int q = warp; q < 80; q += 8) {
        const float* qrow = base + q * 1536 + h * 64;  // broadcast L1 reads
        int j0 = lane, j1 = lane + 32, j2 = lane + 64;
        const float* k0 = &Kt[j0 * 65];
        const float* k1 = &Kt[(j1 < 80 ? j1 : 0) * 65];
        const float* k2 = &Kt[(j2 < 80 ? j2 : 0) * 65];
        float a0 = 0.f, a1 = 0.f, a2 = 0.f;
#pragma unroll
        for (int kk = 0; kk < 64; kk++) {
            float qv = qrow[kk];
            a0 += qv * k0[kk]; a1 += qv * k1[kk]; a2 += qv * k2[kk];
        }
        float s0 = (j0 <= q) ? a0 * 0.125f : -1e30f;
        float s1 = (j1 <= q) ? a1 * 0.125f : -1e30f;
        float s2 = (j2 <= q) ? a2 * 0.125f : -1e30f;
        float m = fmaxf(fmaxf(s0, s1), s2);
#pragma unroll
        for (int o = 16; o; o >>= 1) m = fmaxf(m, __shfl_xor_sync(0xffffffffu, m, o));
        float p0 = (j0 <= q) ? expf(s0 - m) : 0.f;
        float p1 = (j1 <= q) ? expf(s1 - m) : 0.f;
        float p2 = (j2 <= q) ? expf(s2 - m) : 0.f;
        float sum = p0 + p1 + p2;
#pragma unroll
        for (int o = 16; o; o >>= 1) sum += __shfl_xor_sync(0xffffffffu, sum, o);
        float inv = 1.f / sum;
        pr[warp * 80 + j0] = p0 * inv;
        if (j1 < 80) pr[warp * 80 + j1] = p1 * inv;
        if (j2 < 80) pr[warp * 80 + j2] = p2 * inv;
        __syncwarp();
        float o0 = 0.f, o1 = 0.f;
        for (int j = 0; j <= q; j++) {
            float pv = pr[warp * 80 + j];
            o0 += pv * Vs[j * 64 + lane];
            o1 += pv * Vs[j * 64 + 32 + lane];
        }
        out[(size_t)(b * 80 + q) * EDIM + h * 64 + lane] = o0;
        out[(size_t)(b * 80 + q) * EDIM + h * 64 + 32 + lane] = o1;
        __syncwarp();
    }
}

// ---------------- x = LayerNorm(x + add) ; add is [N,E] or broadcast [E] ----------------
__global__ __launch_bounds__(256) void add_ln_kernel(
    float* __restrict__ x, const float* __restrict__ add,
    const float* __restrict__ w, const float* __restrict__ b, int bcast)
{
    int n = blockIdx.x, t = threadIdx.x;
    size_t off = (size_t)n * EDIM;
    float v0 = x[off + t]       + (bcast ? add[t]       : add[off + t]);
    float v1 = x[off + 256 + t] + (bcast ? add[256 + t] : add[off + 256 + t]);
    float s = v0 + v1, ss = v0 * v0 + v1 * v1;
#pragma unroll
    for (int o = 16; o; o >>= 1) {
        s  += __shfl_xor_sync(0xffffffffu, s, o);
        ss += __shfl_xor_sync(0xffffffffu, ss, o);
    }
    __shared__ float rs[8], rss[8];
    if ((t & 31) == 0) { rs[t >> 5] = s; rss[t >> 5] = ss; }
    __syncthreads();
    float tots = 0.f, totss = 0.f;
#pragma unroll
    for (int i = 0; i < 8; i++) { tots += rs[i]; totss += rss[i]; }
    float mean = tots * (1.f / 512.f);
    float var = totss * (1.f / 512.f) - mean * mean;
    float inv = rsqrtf(var + 1e-5f);
    x[off + t]       = (v0 - mean) * inv * w[t] + b[t];
    x[off + 256 + t] = (v1 - mean) * inv * w[256 + t] + b[256 + t];
}

// ---------------- cross-attn collapses to constant vector: c = OW @ v_bias + ob ----------------
__global__ void ca_const_kernel(const float* __restrict__ ow, const float* __restrict__ vb,
                                const float* __restrict__ ob, float* __restrict__ c)
{
    int e = blockIdx.x * blockDim.x + threadIdx.x;
    if (e < EDIM) {
        float s = ob[e];
        for (int f = 0; f < EDIM; f++) s += ow[(size_t)e * EDIM + f] * vb[f];
        c[e] = s;
    }
}

// ---------------- launch ----------------
extern "C" void kernel_launch(void* const* d_in, const int* in_sizes, int n_in,
                              void* d_out, int out_size)
{
    const int*   caps    = (const int*)  d_in[0];
    const float* W_in    = (const float*)d_in[1];
    const float* b_in    = (const float*)d_in[2];
    const float* pos_emb = (const float*)d_in[3];
    const float* sa_in_w  = (const float*)d_in[4];
    const float* sa_in_b  = (const float*)d_in[5];
    const float* sa_out_w = (const float*)d_in[6];
    const float* sa_out_b = (const float*)d_in[7];
    const float* ca_in_b  = (const float*)d_in[9];
    const float* ca_out_w = (const float*)d_in[10];
    const float* ca_out_b = (const float*)d_in[11];
    const float* ff1_w = (const float*)d_in[12];
    const float* ff1_b = (const float*)d_in[13];
    const float* ff2_w = (const float*)d_in[14];
    const float* ff2_b = (const float*)d_in[15];
    const float* ln1_w = (const float*)d_in[16];
    const float* ln1_b = (const float*)d_in[17];
    const float* ln2_w = (const float*)d_in[18];
    const float* ln2_b = (const float*)d_in[19];
    const float* ln3_w = (const float*)d_in[20];
    const float* ln3_b = (const float*)d_in[21];
    const float* out_w = (const float*)d_in[22];
    const float* out_b = (const float*)d_in[23];

    float *x, *qkv, *t512, *h1, *cvec;
    __nv_bfloat16 *ahi, *alo, *bhi, *blo;
    cudaGetSymbolAddress((void**)&x, g_x);
    cudaGetSymbolAddress((void**)&qkv, g_qkv);
    cudaGetSymbolAddress((void**)&t512, g_t512);
    cudaGetSymbolAddress((void**)&h1, g_h1);
    cudaGetSymbolAddress((void**)&cvec, g_c);
    cudaGetSymbolAddress((void**)&ahi, g_ahi);
    cudaGetSymbolAddress((void**)&alo, g_alo);
    cudaGetSymbolAddress((void**)&bhi, g_bhi);
    cudaGetSymbolAddress((void**)&blo, g_blo);

    auto split = [&](const float* src, __nv_bfloat16* h, __nv_bfloat16* l, int nelem) {
        int n4 = nelem / 4;
        split_kernel<<<(n4 + 255) / 256, 256>>>(src, h, l, n4);
    };

    embed_kernel<<<NTOK, 256>>>(caps, W_in, b_in, pos_emb, x);

    for (int i = 0; i < NLAYER; i++) {
        // ---- self attention ----
        split(x, ahi, alo, NTOK * EDIM);
        split(sa_in_w + (size_t)i * 3 * EDIM * EDIM, bhi, blo, 3 * EDIM * EDIM);
        gemm3_kernel<<<dim3(3 * EDIM / 128, NTOK / 128), 256>>>(
            ahi, alo, bhi, blo, sa_in_b + (size_t)i * 3 * EDIM, qkv,
            NTOK, 3 * EDIM, EDIM, 0);
        attn_kernel<<<32 * NHEAD, 256>>>(qkv, t512);
        split(t512, ahi, alo, NTOK * EDIM);
        split(sa_out_w + (size_t)i * EDIM * EDIM, bhi, blo, EDIM * EDIM);
        gemm3_kernel<<<dim3(EDIM / 128, NTOK / 128), 256>>>(
            ahi, alo, bhi, blo, sa_out_b + (size_t)i * EDIM, t512,
            NTOK, EDIM, EDIM, 0);
        add_ln_kernel<<<NTOK, 256>>>(x, t512, ln1_w + i * EDIM, ln1_b + i * EDIM, 0);

        // ---- cross attention (analytically a constant vector) ----
        ca_const_kernel<<<2, 256>>>(ca_out_w + (size_t)i * EDIM * EDIM,
                                    ca_in_b + (size_t)i * 3 * EDIM + 2 * EDIM,
                                    ca_out_b + (size_t)i * EDIM, cvec);
        add_ln_kernel<<<NTOK, 256>>>(x, cvec, ln2_w + i * EDIM, ln2_b + i * EDIM, 1);

        // ---- FFN ----
        split(x, ahi, alo, NTOK * EDIM);
        split(ff1_w + (size_t)i * FFD * EDIM, bhi, blo, FFD * EDIM);
        gemm3_kernel<<<dim3(FFD / 128, NTOK / 128), 256>>>(
            ahi, alo, bhi, blo, ff1_b + (size_t)i * FFD, h1,
            NTOK, FFD, EDIM, 1);
        split(h1, ahi, alo, NTOK * FFD);
        split(ff2_w + (size_t)i * EDIM * FFD, bhi, blo, EDIM * FFD);
        gemm3_kernel<<<dim3(EDIM / 128, NTOK / 128), 256>>>(
            ahi, alo, bhi, blo, ff2_b + (size_t)i * EDIM, t512,
            NTOK, EDIM, FFD, 0);
        add_ln_kernel<<<NTOK, 256>>>(x, t512, ln3_w + i * EDIM, ln3_b + i * EDIM, 0);
    }

    // ---- output head ----
    split(x, ahi, alo, NTOK * EDIM);
    split(out_w, bhi, blo, VOC * EDIM);
    gemm3_kernel<<<dim3(VOC / 128, NTOK / 128), 256>>>(
        ahi, alo, bhi, blo, out_b, (float*)d_out, NTOK, VOC, EDIM, 0);
}

// round 3
// speedup vs baseline: 1.7739x; 1.7739x over previous
#include <cuda_runtime.h>
#include <cuda_fp16.h>
#include <cstdint>

#define NTOK 2560
#define EDIM 512
#define NHEAD 8
#define HDIM 64
#define FFD 2048
#define VOC 32000
#define SEQ 80
#define NLAYER 4

#define BM 128
#define BN 128
#define BK 64
#define STAGES 3
// per stage: Ahi 16K | Alo 16K | B 16K
#define STAGE_BYTES 49152
#define SMEM_DYN (STAGES * STAGE_BYTES)

// ---------------- device scratch (no allocations allowed) ----------------
__device__ float g_x[NTOK * EDIM];
__device__ float g_qkv[NTOK * 3 * EDIM];
__device__ float g_t512[NTOK * EDIM];
__device__ float g_h1[NTOK * FFD];
__device__ float g_c[EDIM];
__device__ __half g_ahi[NTOK * FFD];
__device__ __half g_alo[NTOK * FFD];
__device__ __half g_wsain[NLAYER * 3 * EDIM * EDIM];
__device__ __half g_wsaout[NLAYER * EDIM * EDIM];
__device__ __half g_wff1[NLAYER * FFD * EDIM];
__device__ __half g_wff2[NLAYER * EDIM * FFD];
__device__ __half g_wout[(size_t)VOC * EDIM];

// ---------------- PTX helpers ----------------
__device__ __forceinline__ uint32_t smem_u32(const void* p) {
    uint32_t a;
    asm("{ .reg .u64 t; cvta.to.shared.u64 t, %1; cvt.u32.u64 %0, t; }" : "=r"(a) : "l"(p));
    return a;
}
__device__ __forceinline__ void cp16(uint32_t dst, const void* src) {
    asm volatile("cp.async.cg.shared.global [%0], [%1], 16;\n" :: "r"(dst), "l"(src));
}
__device__ __forceinline__ void cp_commit() { asm volatile("cp.async.commit_group;\n" ::: "memory"); }
template <int N>
__device__ __forceinline__ void cp_wait() { asm volatile("cp.async.wait_group %0;\n" :: "n"(N) : "memory"); }

__device__ __forceinline__ void ldsm4(uint32_t r[4], uint32_t addr) {
    asm volatile("ldmatrix.sync.aligned.m8n8.x4.shared.b16 {%0,%1,%2,%3},[%4];\n"
                 : "=r"(r[0]), "=r"(r[1]), "=r"(r[2]), "=r"(r[3]) : "r"(addr));
}
__device__ __forceinline__ void mma16816(float d[4], const uint32_t a[4], const uint32_t b[2]) {
    asm volatile(
        "mma.sync.aligned.m16n8k16.row.col.f32.f16.f16.f32 "
        "{%0,%1,%2,%3},{%4,%5,%6,%7},{%8,%9},{%0,%1,%2,%3};\n"
        : "+f"(d[0]), "+f"(d[1]), "+f"(d[2]), "+f"(d[3])
        : "r"(a[0]), "r"(a[1]), "r"(a[2]), "r"(a[3]), "r"(b[0]), "r"(b[1]));
}

__device__ __forceinline__ uint32_t swz(uint32_t off) { return off ^ ((off >> 3) & 0x70); }

// ---------------- pipelined HMMA GEMM ----------------
// C[M,N] = (Ahi+Alo)[M,K] @ B[N,K]^T + bias  (2-pass fp16 split on A, B fp16-rounded)
__global__ __launch_bounds__(512, 1) void gemm_hmma(
    const __half* __restrict__ Ahi, const __half* __restrict__ Alo,
    const __half* __restrict__ B, const float* __restrict__ bias,
    float* __restrict__ C, int M, int N, int K, int dorelu)
{
    extern __shared__ __align__(16) char sm[];
    const int tid = threadIdx.x, lane = tid & 31, warp = tid >> 5;
    const int bm = blockIdx.x * BM, bn = blockIdx.y * BN;
    const int wm = (warp & 3) * 32, wn = (warp >> 2) * 32;
    const uint32_t smem0 = smem_u32(sm);

    float acc[2][4][4] = {};

    const int S = K / BK;

    auto load_stage = [&](int st, int k0) {
        uint32_t b0 = smem0 + (uint32_t)st * STAGE_BYTES;
#pragma unroll
        for (int i = tid; i < 1024; i += 512) {
            int r = i >> 3, cb = (i & 7) * 16;
            uint32_t sw = swz(r * 128 + cb);
            const char* pa = (const char*)(Ahi + (size_t)(bm + r) * K + k0) + cb;
            const char* pl = (const char*)(Alo + (size_t)(bm + r) * K + k0) + cb;
            const char* pb = (const char*)(B + (size_t)(bn + r) * K + k0) + cb;
            cp16(b0 + sw, pa);
            cp16(b0 + 16384 + sw, pl);
            cp16(b0 + 32768 + sw, pb);
        }
    };

#pragma unroll
    for (int s = 0; s < STAGES; s++) {
        if (s < S) load_stage(s, s * BK);
        cp_commit();
    }

    for (int s = 0; s < S; s++) {
        cp_wait<STAGES - 1>();
        __syncthreads();
        uint32_t b0 = smem0 + (uint32_t)(s % STAGES) * STAGE_BYTES;
        uint32_t aH = b0, aL = b0 + 16384, bB = b0 + 32768;
#pragma unroll
        for (int kc = 0; kc < 4; kc++) {
            const int kb = kc * 32;  // byte offset of 16-half k-chunk
            uint32_t bfr[4][2];
            {
                int lrow = lane & 7, seg = lane >> 3;
#pragma unroll
                for (int nt = 0; nt < 4; nt += 2) {
                    uint32_t t4[4];
                    uint32_t addr = bB + swz((wn + (nt + (seg >> 1)) * 8 + lrow) * 128 +
                                             kb + (seg & 1) * 16);
                    ldsm4(t4, addr);
                    bfr[nt][0] = t4[0]; bfr[nt][1] = t4[1];
                    bfr[nt + 1][0] = t4[2]; bfr[nt + 1][1] = t4[3];
                }
            }
#pragma unroll
            for (int pass = 0; pass < 2; pass++) {
                uint32_t ab = pass ? aL : aH;
#pragma unroll
                for (int mt = 0; mt < 2; mt++) {
                    uint32_t af[4];
                    uint32_t addr = ab + swz((wm + mt * 16 + (lane & 15)) * 128 +
                                             kb + (lane >> 4) * 16);
                    ldsm4(af, addr);
#pragma unroll
                    for (int nt = 0; nt < 4; nt++) mma16816(acc[mt][nt], af, bfr[nt]);
                }
            }
        }
        __syncthreads();
        if (s + STAGES < S) load_stage(s % STAGES, (s + STAGES) * BK);
        cp_commit();
    }

    // epilogue
#pragma unroll
    for (int mt = 0; mt < 2; mt++) {
#pragma unroll
        for (int nt = 0; nt < 4; nt++) {
            int row = bm + wm + mt * 16 + (lane >> 2);
            int col = bn + wn + nt * 8 + (lane & 3) * 2;
            float b0 = bias[col], b1 = bias[col + 1];
            float v0 = acc[mt][nt][0] + b0, v1 = acc[mt][nt][1] + b1;
            float v2 = acc[mt][nt][2] + b0, v3 = acc[mt][nt][3] + b1;
            if (dorelu) {
                v0 = fmaxf(v0, 0.f); v1 = fmaxf(v1, 0.f);
                v2 = fmaxf(v2, 0.f); v3 = fmaxf(v3, 0.f);
            }
            *(float2*)&C[(size_t)row * N + col] = make_float2(v0, v1);
            *(float2*)&C[(size_t)(row + 8) * N + col] = make_float2(v2, v3);
        }
    }
}

// ---------------- fp32 -> fp16 hi/lo split (activations) ----------------
__global__ void splitA_kernel(const float* __restrict__ s, __half* __restrict__ hi,
                              __half* __restrict__ lo, int n4)
{
    int i = blockIdx.x * blockDim.x + threadIdx.x;
    if (i >= n4) return;
    float4 v = ((const float4*)s)[i];
    __half h0 = __float2half_rn(v.x), h1 = __float2half_rn(v.y);
    __half h2 = __float2half_rn(v.z), h3 = __float2half_rn(v.w);
    ((__half2*)hi)[2 * i]     = __halves2half2(h0, h1);
    ((__half2*)hi)[2 * i + 1] = __halves2half2(h2, h3);
    ((__half2*)lo)[2 * i] = __halves2half2(
        __float2half_rn(v.x - __half2float(h0)), __float2half_rn(v.y - __half2float(h1)));
    ((__half2*)lo)[2 * i + 1] = __halves2half2(
        __float2half_rn(v.z - __half2float(h2)), __float2half_rn(v.w - __half2float(h3)));
}

// ---------------- fp32 -> fp16 round (weights) ----------------
__global__ void convB_kernel(const float* __restrict__ s, __half* __restrict__ o, int n4)
{
    int i = blockIdx.x * blockDim.x + threadIdx.x;
    if (i >= n4) return;
    float4 v = ((const float4*)s)[i];
    ((__half2*)o)[2 * i]     = __floats2half2_rn(v.x, v.y);
    ((__half2*)o)[2 * i + 1] = __floats2half2_rn(v.z, v.w);
}

// ---------------- embedding gather ----------------
__global__ __launch_bounds__(256) void embed_kernel(
    const int* __restrict__ caps, const float* __restrict__ Win,
    const float* __restrict__ bin, const float* __restrict__ pos, float* __restrict__ x)
{
    int n = blockIdx.x;
    int tok = caps[n];
    int l = n % SEQ;
#pragma unroll
    for (int e = threadIdx.x; e < EDIM; e += 256)
        x[(size_t)n * EDIM + e] = Win[(size_t)e * VOC + tok] + bin[e] + pos[l * EDIM + e];
}

// ---------------- causal self-attention (fp32, one block per (b,h)) ----------------
__global__ __launch_bounds__(256) void attn_kernel(const float* __restrict__ qkv,
                                                   float* __restrict__ out)
{
    int b = blockIdx.x >> 3, h = blockIdx.x & 7;
    __shared__ float Kt[80 * 65];
    __shared__ float Vs[80 * 64];
    __shared__ float pr[8 * 80];
    const float* base = qkv + (size_t)b * SEQ * 3 * EDIM;
    for (int i = threadIdx.x; i < 80 * 64; i += 256) {
        int t = i >> 6, d = i & 63;
        Kt[t * 65 + d] = base[t * 1536 + 512 + h * 64 + d];
        Vs[i]          = base[t * 1536 + 1024 + h * 64 + d];
    }
    __syncthreads();
    int warp = threadIdx.x >> 5, lane = threadIdx.x & 31;
    for (int q = warp; q < 80; q += 8) {
        const float* qrow = base + q * 1536 + h * 64;
        int j0 = lane, j1 = lane + 32, j2 = lane + 64;
        const float* k0 = &Kt[j0 * 65];
        const float* k1 = &Kt[(j1 < 80 ? j1 : 0) * 65];
        const float* k2 = &Kt[(j2 < 80 ? j2 : 0) * 65];
        float a0 = 0.f, a1 = 0.f, a2 = 0.f;
#pragma unroll
        for (int kk = 0; kk < 64; kk++) {
            float qv = qrow[kk];
            a0 += qv * k0[kk]; a1 += qv * k1[kk]; a2 += qv * k2[kk];
        }
        float s0 = (j0 <= q) ? a0 * 0.125f : -1e30f;
        float s1 = (j1 <= q) ? a1 * 0.125f : -1e30f;
        float s2 = (j2 <= q) ? a2 * 0.125f : -1e30f;
        float m = fmaxf(fmaxf(s0, s1), s2);
#pragma unroll
        for (int o = 16; o; o >>= 1) m = fmaxf(m, __shfl_xor_sync(0xffffffffu, m, o));
        float p0 = (j0 <= q) ? expf(s0 - m) : 0.f;
        float p1 = (j1 <= q) ? expf(s1 - m) : 0.f;
        float p2 = (j2 <= q) ? expf(s2 - m) : 0.f;
        float sum = p0 + p1 + p2;
#pragma unroll
        for (int o = 16; o; o >>= 1) sum += __shfl_xor_sync(0xffffffffu, sum, o);
        float inv = 1.f / sum;
        pr[warp * 80 + j0] = p0 * inv;
        if (j1 < 80) pr[warp * 80 + j1] = p1 * inv;
        if (j2 < 80) pr[warp * 80 + j2] = p2 * inv;
        __syncwarp();
        float o0 = 0.f, o1 = 0.f;
        for (int j = 0; j <= q; j++) {
            float pv = pr[warp * 80 + j];
            o0 += pv * Vs[j * 64 + lane];
            o1 += pv * Vs[j * 64 + 32 + lane];
        }
        out[(size_t)(b * 80 + q) * EDIM + h * 64 + lane] = o0;
        out[(size_t)(b * 80 + q) * EDIM + h * 64 + 32 + lane] = o1;
        __syncwarp();
    }
}

// ---------------- x = LayerNorm(x + add) ----------------
__global__ __launch_bounds__(256) void add_ln_kernel(
    float* __restrict__ x, const float* __restrict__ add,
    const float* __restrict__ w, const float* __restrict__ b, int bcast)
{
    int n = blockIdx.x, t = threadIdx.x;
    size_t off = (size_t)n * EDIM;
    float v0 = x[off + t]       + (bcast ? add[t]       : add[off + t]);
    float v1 = x[off + 256 + t] + (bcast ? add[256 + t] : add[off + 256 + t]);
    float s = v0 + v1, ss = v0 * v0 + v1 * v1;
#pragma unroll
    for (int o = 16; o; o >>= 1) {
        s  += __shfl_xor_sync(0xffffffffu, s, o);
        ss += __shfl_xor_sync(0xffffffffu, ss, o);
    }
    __shared__ float rs[8], rss[8];
    if ((t & 31) == 0) { rs[t >> 5] = s; rss[t >> 5] = ss; }
    __syncthreads();
    float tots = 0.f, totss = 0.f;
#pragma unroll
    for (int i = 0; i < 8; i++) { tots += rs[i]; totss += rss[i]; }
    float mean = tots * (1.f / 512.f);
    float var = totss * (1.f / 512.f) - mean * mean;
    float inv = rsqrtf(var + 1e-5f);
    x[off + t]       = (v0 - mean) * inv * w[t] + b[t];
    x[off + 256 + t] = (v1 - mean) * inv * w[256 + t] + b[256 + t];
}

// ---------------- cross-attn constant vector: warp-per-output ----------------
__global__ void ca_const_kernel(const float* __restrict__ ow, const float* __restrict__ vb,
                                const float* __restrict__ ob, float* __restrict__ c)
{
    int gw = (blockIdx.x * blockDim.x + threadIdx.x) >> 5;
    int lane = threadIdx.x & 31;
    if (gw >= EDIM) return;
    float s = 0.f;
#pragma unroll
    for (int f = lane; f < EDIM; f += 32) s += ow[(size_t)gw * EDIM + f] * vb[f];
#pragma unroll
    for (int o = 16; o; o >>= 1) s += __shfl_xor_sync(0xffffffffu, s, o);
    if (lane == 0) c[gw] = ob[gw] + s;
}

// ---------------- launch ----------------
extern "C" void kernel_launch(void* const* d_in, const int* in_sizes, int n_in,
                              void* d_out, int out_size)
{
    const int*   caps    = (const int*)  d_in[0];
    const float* W_in    = (const float*)d_in[1];
    const float* b_in    = (const float*)d_in[2];
    const float* pos_emb = (const float*)d_in[3];
    const float* sa_in_w  = (const float*)d_in[4];
    const float* sa_in_b  = (const float*)d_in[5];
    const float* sa_out_w = (const float*)d_in[6];
    const float* sa_out_b = (const float*)d_in[7];
    const float* ca_in_b  = (const float*)d_in[9];
    const float* ca_out_w = (const float*)d_in[10];
    const float* ca_out_b = (const float*)d_in[11];
    const float* ff1_w = (const float*)d_in[12];
    const float* ff1_b = (const float*)d_in[13];
    const float* ff2_w = (const float*)d_in[14];
    const float* ff2_b = (const float*)d_in[15];
    const float* ln1_w = (const float*)d_in[16];
    const float* ln1_b = (const float*)d_in[17];
    const float* ln2_w = (const float*)d_in[18];
    const float* ln2_b = (const float*)d_in[19];
    const float* ln3_w = (const float*)d_in[20];
    const float* ln3_b = (const float*)d_in[21];
    const float* out_w = (const float*)d_in[22];
    const float* out_b = (const float*)d_in[23];

    float *x, *qkv, *t512, *h1, *cvec;
    __half *ahi, *alo, *wsain, *wsaout, *wff1, *wff2, *wout;
    cudaGetSymbolAddress((void**)&x, g_x);
    cudaGetSymbolAddress((void**)&qkv, g_qkv);
    cudaGetSymbolAddress((void**)&t512, g_t512);
    cudaGetSymbolAddress((void**)&h1, g_h1);
    cudaGetSymbolAddress((void**)&cvec, g_c);
    cudaGetSymbolAddress((void**)&ahi, g_ahi);
    cudaGetSymbolAddress((void**)&alo, g_alo);
    cudaGetSymbolAddress((void**)&wsain, g_wsain);
    cudaGetSymbolAddress((void**)&wsaout, g_wsaout);
    cudaGetSymbolAddress((void**)&wff1, g_wff1);
    cudaGetSymbolAddress((void**)&wff2, g_wff2);
    cudaGetSymbolAddress((void**)&wout, g_wout);

    cudaFuncSetAttribute(gemm_hmma, cudaFuncAttributeMaxDynamicSharedMemorySize, SMEM_DYN);

    auto conv = [&](const float* src, __half* dst, size_t nelem) {
        int n4 = (int)(nelem / 4);
        convB_kernel<<<(n4 + 255) / 256, 256>>>(src, dst, n4);
    };
    auto split = [&](const float* src, int nelem) {
        int n4 = nelem / 4;
        splitA_kernel<<<(n4 + 255) / 256, 256>>>(src, ahi, alo, n4);
    };
    auto gemm = [&](const __half* Bw, const float* bias, float* C,
                    int M, int N, int K, int relu) {
        gemm_hmma<<<dim3(M / BM, N / BN), 512, SMEM_DYN>>>(ahi, alo, Bw, bias, C, M, N, K, relu);
    };

    // bulk weight conversion (once per launch, big coalesced kernels)
    conv(sa_in_w,  wsain,  (size_t)NLAYER * 3 * EDIM * EDIM);
    conv(sa_out_w, wsaout, (size_t)NLAYER * EDIM * EDIM);
    conv(ff1_w,    wff1,   (size_t)NLAYER * FFD * EDIM);
    conv(ff2_w,    wff2,   (size_t)NLAYER * EDIM * FFD);
    conv(out_w,    wout,   (size_t)VOC * EDIM);

    embed_kernel<<<NTOK, 256>>>(caps, W_in, b_in, pos_emb, x);

    for (int i = 0; i < NLAYER; i++) {
        // ---- self attention ----
        split(x, NTOK * EDIM);
        gemm(wsain + (size_t)i * 3 * EDIM * EDIM, sa_in_b + (size_t)i * 3 * EDIM,
             qkv, NTOK, 3 * EDIM, EDIM, 0);
        attn_kernel<<<32 * NHEAD, 256>>>(qkv, t512);
        split(t512, NTOK * EDIM);
        gemm(wsaout + (size_t)i * EDIM * EDIM, sa_out_b + (size_t)i * EDIM,
             t512, NTOK, EDIM, EDIM, 0);
        add_ln_kernel<<<NTOK, 256>>>(x, t512, ln1_w + i * EDIM, ln1_b + i * EDIM, 0);

        // ---- cross attention (constant vector) ----
        ca_const_kernel<<<64, 256>>>(ca_out_w + (size_t)i * EDIM * EDIM,
                                     ca_in_b + (size_t)i * 3 * EDIM + 2 * EDIM,
                                     ca_out_b + (size_t)i * EDIM, cvec);
        add_ln_kernel<<<NTOK, 256>>>(x, cvec, ln2_w + i * EDIM, ln2_b + i * EDIM, 1);

        // ---- FFN ----
        split(x, NTOK * EDIM);
        gemm(wff1 + (size_t)i * FFD * EDIM, ff1_b + (size_t)i * FFD,
             h1, NTOK, FFD, EDIM, 1);
        split(h1, NTOK * FFD);
        gemm(wff2 + (size_t)i * EDIM * FFD, ff2_b + (size_t)i * EDIM,
             t512, NTOK, EDIM, FFD, 0);
        add_ln_kernel<<<NTOK, 256>>>(x, t512, ln3_w + i * EDIM, ln3_b + i * EDIM, 0);
    }

    // ---- output head ----
    split(x, NTOK * EDIM);
    gemm(wout, out_b, (float*)d_out, NTOK, VOC, EDIM, 0);
}

// round 4
// speedup vs baseline: 2.4397x; 1.3753x over previous
#include <cuda_runtime.h>
#include <cuda_fp16.h>
#include <cstdint>

#define NTOK 2560
#define EDIM 512
#define NHEAD 8
#define HDIM 64
#define FFD 2048
#define VOC 32000
#define SEQ 80
#define NLAYER 4

#define BM 128
#define BN 128
#define BK 64
#define STAGES 4
// per stage: A 16K | B 16K
#define STAGE_BYTES 32768
#define SMEM_DYN (STAGES * STAGE_BYTES)

// ---------------- device scratch (no allocations allowed) ----------------
__device__ float g_x[NTOK * EDIM];
__device__ float g_qkv[NTOK * 3 * EDIM];
__device__ float g_t512[NTOK * EDIM];
__device__ float g_c[EDIM];
__device__ __half g_xh[NTOK * EDIM];
__device__ __half g_t512h[NTOK * EDIM];
__device__ __half g_h1h[NTOK * FFD];
__device__ __half g_wsain[NLAYER * 3 * EDIM * EDIM];
__device__ __half g_wsaout[NLAYER * EDIM * EDIM];
__device__ __half g_wff1[NLAYER * FFD * EDIM];
__device__ __half g_wff2[NLAYER * EDIM * FFD];
__device__ __half g_wout[(size_t)VOC * EDIM];

// ---------------- PTX helpers ----------------
__device__ __forceinline__ uint32_t smem_u32(const void* p) {
    uint32_t a;
    asm("{ .reg .u64 t; cvta.to.shared.u64 t, %1; cvt.u32.u64 %0, t; }" : "=r"(a) : "l"(p));
    return a;
}
__device__ __forceinline__ void cp16(uint32_t dst, const void* src) {
    asm volatile("cp.async.cg.shared.global [%0], [%1], 16;\n" :: "r"(dst), "l"(src));
}
__device__ __forceinline__ void cp_commit() { asm volatile("cp.async.commit_group;\n" ::: "memory"); }
template <int N>
__device__ __forceinline__ void cp_wait() { asm volatile("cp.async.wait_group %0;\n" :: "n"(N) : "memory"); }

__device__ __forceinline__ void ldsm4(uint32_t r[4], uint32_t addr) {
    asm volatile("ldmatrix.sync.aligned.m8n8.x4.shared.b16 {%0,%1,%2,%3},[%4];\n"
                 : "=r"(r[0]), "=r"(r[1]), "=r"(r[2]), "=r"(r[3]) : "r"(addr));
}
__device__ __forceinline__ void mma16816(float d[4], const uint32_t a[4], const uint32_t b[2]) {
    asm volatile(
        "mma.sync.aligned.m16n8k16.row.col.f32.f16.f16.f32 "
        "{%0,%1,%2,%3},{%4,%5,%6,%7},{%8,%9},{%0,%1,%2,%3};\n"
        : "+f"(d[0]), "+f"(d[1]), "+f"(d[2]), "+f"(d[3])
        : "r"(a[0]), "r"(a[1]), "r"(a[2]), "r"(a[3]), "r"(b[0]), "r"(b[1]));
}

__device__ __forceinline__ uint32_t swz(uint32_t off) { return off ^ ((off >> 3) & 0x70); }

// ---------------- pipelined single-pass fp16 HMMA GEMM ----------------
// C[M,N] = A[M,K] @ B[N,K]^T + bias ; writes fp32 C (if non-null) and/or fp16 Ch
__global__ __launch_bounds__(512, 1) void gemm_hmma(
    const __half* __restrict__ A, const __half* __restrict__ B,
    const float* __restrict__ bias, float* __restrict__ C, __half* __restrict__ Ch,
    int M, int N, int K, int dorelu)
{
    extern __shared__ __align__(16) char sm[];
    const int tid = threadIdx.x, lane = tid & 31, warp = tid >> 5;
    const int bm = blockIdx.x * BM, bn = blockIdx.y * BN;
    const int wm = (warp & 3) * 32, wn = (warp >> 2) * 32;
    const uint32_t smem0 = smem_u32(sm);

    float acc[2][4][4] = {};
    const int S = K / BK;

    auto load_stage = [&](int st, int k0) {
        uint32_t b0 = smem0 + (uint32_t)st * STAGE_BYTES;
#pragma unroll
        for (int i = tid; i < 1024; i += 512) {
            int r = i >> 3, cb = (i & 7) * 16;
            uint32_t sw = swz(r * 128 + cb);
            const char* pa = (const char*)(A + (size_t)(bm + r) * K + k0) + cb;
            const char* pb = (const char*)(B + (size_t)(bn + r) * K + k0) + cb;
            cp16(b0 + sw, pa);
            cp16(b0 + 16384 + sw, pb);
        }
    };

#pragma unroll
    for (int s = 0; s < STAGES; s++) {
        if (s < S) load_stage(s, s * BK);
        cp_commit();
    }

    for (int s = 0; s < S; s++) {
        cp_wait<STAGES - 1>();
        __syncthreads();
        uint32_t b0 = smem0 + (uint32_t)(s % STAGES) * STAGE_BYTES;
        uint32_t aA = b0, bB = b0 + 16384;
#pragma unroll
        for (int kc = 0; kc < 4; kc++) {
            const int kb = kc * 32;  // byte offset of 16-half k-chunk
            uint32_t bfr[4][2];
            {
                int lrow = lane & 7, seg = lane >> 3;
#pragma unroll
                for (int nt = 0; nt < 4; nt += 2) {
                    uint32_t t4[4];
                    uint32_t addr = bB + swz((wn + (nt + (seg >> 1)) * 8 + lrow) * 128 +
                                             kb + (seg & 1) * 16);
                    ldsm4(t4, addr);
                    bfr[nt][0] = t4[0]; bfr[nt][1] = t4[1];
                    bfr[nt + 1][0] = t4[2]; bfr[nt + 1][1] = t4[3];
                }
            }
#pragma unroll
            for (int mt = 0; mt < 2; mt++) {
                uint32_t af[4];
                uint32_t addr = aA + swz((wm + mt * 16 + (lane & 15)) * 128 +
                                         kb + (lane >> 4) * 16);
                ldsm4(af, addr);
#pragma unroll
                for (int nt = 0; nt < 4; nt++) mma16816(acc[mt][nt], af, bfr[nt]);
            }
        }
        __syncthreads();
        if (s + STAGES < S) load_stage(s % STAGES, (s + STAGES) * BK);
        cp_commit();
    }

    // epilogue
#pragma unroll
    for (int mt = 0; mt < 2; mt++) {
#pragma unroll
        for (int nt = 0; nt < 4; nt++) {
            int row = bm + wm + mt * 16 + (lane >> 2);
            int col = bn + wn + nt * 8 + (lane & 3) * 2;
            float b0 = bias[col], b1 = bias[col + 1];
            float v0 = acc[mt][nt][0] + b0, v1 = acc[mt][nt][1] + b1;
            float v2 = acc[mt][nt][2] + b0, v3 = acc[mt][nt][3] + b1;
            if (dorelu) {
                v0 = fmaxf(v0, 0.f); v1 = fmaxf(v1, 0.f);
                v2 = fmaxf(v2, 0.f); v3 = fmaxf(v3, 0.f);
            }
            if (C) {
                *(float2*)&C[(size_t)row * N + col] = make_float2(v0, v1);
                *(float2*)&C[(size_t)(row + 8) * N + col] = make_float2(v2, v3);
            }
            if (Ch) {
                *(__half2*)&Ch[(size_t)row * N + col] = __floats2half2_rn(v0, v1);
                *(__half2*)&Ch[(size_t)(row + 8) * N + col] = __floats2half2_rn(v2, v3);
            }
        }
    }
}

// ---------------- fp32 -> fp16 round (weights) ----------------
__global__ void convB_kernel(const float* __restrict__ s, __half* __restrict__ o, int n4)
{
    int i = blockIdx.x * blockDim.x + threadIdx.x;
    if (i >= n4) return;
    float4 v = ((const float4*)s)[i];
    ((__half2*)o)[2 * i]     = __floats2half2_rn(v.x, v.y);
    ((__half2*)o)[2 * i + 1] = __floats2half2_rn(v.z, v.w);
}

// ---------------- embedding gather (writes fp32 + fp16) ----------------
__global__ __launch_bounds__(256) void embed_kernel(
    const int* __restrict__ caps, const float* __restrict__ Win,
    const float* __restrict__ bin, const float* __restrict__ pos,
    float* __restrict__ x, __half* __restrict__ xh)
{
    int n = blockIdx.x;
    int tok = caps[n];
    int l = n % SEQ;
#pragma unroll
    for (int e = threadIdx.x; e < EDIM; e += 256) {
        float v = Win[(size_t)e * VOC + tok] + bin[e] + pos[l * EDIM + e];
        x[(size_t)n * EDIM + e] = v;
        xh[(size_t)n * EDIM + e] = __float2half_rn(v);
    }
}

// ---------------- causal self-attention (fp32 math, fp16 out) ----------------
__global__ __launch_bounds__(256) void attn_kernel(const float* __restrict__ qkv,
                                                   __half* __restrict__ out)
{
    int b = blockIdx.x >> 3, h = blockIdx.x & 7;
    __shared__ float Kt[80 * 65];
    __shared__ float Vs[80 * 64];
    __shared__ float pr[8 * 80];
    const float* base = qkv + (size_t)b * SEQ * 3 * EDIM;
    for (int i = threadIdx.x; i < 80 * 64; i += 256) {
        int t = i >> 6, d = i & 63;
        Kt[t * 65 + d] = base[t * 1536 + 512 + h * 64 + d];
        Vs[i]          = base[t * 1536 + 1024 + h * 64 + d];
    }
    __syncthreads();
    int warp = threadIdx.x >> 5, lane = threadIdx.x & 31;
    for (int q = warp; q < 80; q += 8) {
        const float* qrow = base + q * 1536 + h * 64;
        int j0 = lane, j1 = lane + 32, j2 = lane + 64;
        const float* k0 = &Kt[j0 * 65];
        const float* k1 = &Kt[(j1 < 80 ? j1 : 0) * 65];
        const float* k2 = &Kt[(j2 < 80 ? j2 : 0) * 65];
        float a0 = 0.f, a1 = 0.f, a2 = 0.f;
#pragma unroll
        for (int kk = 0; kk < 64; kk++) {
            float qv = qrow[kk];
            a0 += qv * k0[kk]; a1 += qv * k1[kk]; a2 += qv * k2[kk];
        }
        float s0 = (j0 <= q) ? a0 * 0.125f : -1e30f;
        float s1 = (j1 <= q) ? a1 * 0.125f : -1e30f;
        float s2 = (j2 <= q) ? a2 * 0.125f : -1e30f;
        float m = fmaxf(fmaxf(s0, s1), s2);
#pragma unroll
        for (int o = 16; o; o >>= 1) m = fmaxf(m, __shfl_xor_sync(0xffffffffu, m, o));
        float p0 = (j0 <= q) ? expf(s0 - m) : 0.f;
        float p1 = (j1 <= q) ? expf(s1 - m) : 0.f;
        float p2 = (j2 <= q) ? expf(s2 - m) : 0.f;
        float sum = p0 + p1 + p2;
#pragma unroll
        for (int o = 16; o; o >>= 1) sum += __shfl_xor_sync(0xffffffffu, sum, o);
        float inv = 1.f / sum;
        pr[warp * 80 + j0] = p0 * inv;
        if (j1 < 80) pr[warp * 80 + j1] = p1 * inv;
        if (j2 < 80) pr[warp * 80 + j2] = p2 * inv;
        __syncwarp();
        float o0 = 0.f, o1 = 0.f;
        for (int j = 0; j <= q; j++) {
            float pv = pr[warp * 80 + j];
            o0 += pv * Vs[j * 64 + lane];
            o1 += pv * Vs[j * 64 + 32 + lane];
        }
        out[(size_t)(b * 80 + q) * EDIM + h * 64 + lane] = __float2half_rn(o0);
        out[(size_t)(b * 80 + q) * EDIM + h * 64 + 32 + lane] = __float2half_rn(o1);
        __syncwarp();
    }
}

// ---------------- x = LayerNorm(x + add); writes fp32 x and fp16 xh ----------------
__global__ __launch_bounds__(256) void add_ln_kernel(
    float* __restrict__ x, __half* __restrict__ xh, const float* __restrict__ add,
    const float* __restrict__ w, const float* __restrict__ b, int bcast)
{
    int n = blockIdx.x, t = threadIdx.x;
    size_t off = (size_t)n * EDIM;
    float v0 = x[off + t]       + (bcast ? add[t]       : add[off + t]);
    float v1 = x[off + 256 + t] + (bcast ? add[256 + t] : add[off + 256 + t]);
    float s = v0 + v1, ss = v0 * v0 + v1 * v1;
#pragma unroll
    for (int o = 16; o; o >>= 1) {
        s  += __shfl_xor_sync(0xffffffffu, s, o);
        ss += __shfl_xor_sync(0xffffffffu, ss, o);
    }
    __shared__ float rs[8], rss[8];
    if ((t & 31) == 0) { rs[t >> 5] = s; rss[t >> 5] = ss; }
    __syncthreads();
    float tots = 0.f, totss = 0.f;
#pragma unroll
    for (int i = 0; i < 8; i++) { tots += rs[i]; totss += rss[i]; }
    float mean = tots * (1.f / 512.f);
    float var = totss * (1.f / 512.f) - mean * mean;
    float inv = rsqrtf(var + 1e-5f);
    float o0 = (v0 - mean) * inv * w[t] + b[t];
    float o1 = (v1 - mean) * inv * w[256 + t] + b[256 + t];
    x[off + t] = o0;
    x[off + 256 + t] = o1;
    xh[off + t] = __float2half_rn(o0);
    xh[off + 256 + t] = __float2half_rn(o1);
}

// ---------------- cross-attn constant vector: warp-per-output ----------------
__global__ void ca_const_kernel(const float* __restrict__ ow, const float* __restrict__ vb,
                                const float* __restrict__ ob, float* __restrict__ c)
{
    int gw = (blockIdx.x * blockDim.x + threadIdx.x) >> 5;
    int lane = threadIdx.x & 31;
    if (gw >= EDIM) return;
    float s = 0.f;
#pragma unroll
    for (int f = lane; f < EDIM; f += 32) s += ow[(size_t)gw * EDIM + f] * vb[f];
#pragma unroll
    for (int o = 16; o; o >>= 1) s += __shfl_xor_sync(0xffffffffu, s, o);
    if (lane == 0) c[gw] = ob[gw] + s;
}

// ---------------- launch ----------------
extern "C" void kernel_launch(void* const* d_in, const int* in_sizes, int n_in,
                              void* d_out, int out_size)
{
    const int*   caps    = (const int*)  d_in[0];
    const float* W_in    = (const float*)d_in[1];
    const float* b_in    = (const float*)d_in[2];
    const float* pos_emb = (const float*)d_in[3];
    const float* sa_in_w  = (const float*)d_in[4];
    const float* sa_in_b  = (const float*)d_in[5];
    const float* sa_out_w = (const float*)d_in[6];
    const float* sa_out_b = (const float*)d_in[7];
    const float* ca_in_b  = (const float*)d_in[9];
    const float* ca_out_w = (const float*)d_in[10];
    const float* ca_out_b = (const float*)d_in[11];
    const float* ff1_w = (const float*)d_in[12];
    const float* ff1_b = (const float*)d_in[13];
    const float* ff2_w = (const float*)d_in[14];
    const float* ff2_b = (const float*)d_in[15];
    const float* ln1_w = (const float*)d_in[16];
    const float* ln1_b = (const float*)d_in[17];
    const float* ln2_w = (const float*)d_in[18];
    const float* ln2_b = (const float*)d_in[19];
    const float* ln3_w = (const float*)d_in[20];
    const float* ln3_b = (const float*)d_in[21];
    const float* out_w = (const float*)d_in[22];
    const float* out_b = (const float*)d_in[23];

    float *x, *qkv, *t512, *cvec;
    __half *xh, *t512h, *h1h, *wsain, *wsaout, *wff1, *wff2, *wout;
    cudaGetSymbolAddress((void**)&x, g_x);
    cudaGetSymbolAddress((void**)&qkv, g_qkv);
    cudaGetSymbolAddress((void**)&t512, g_t512);
    cudaGetSymbolAddress((void**)&cvec, g_c);
    cudaGetSymbolAddress((void**)&xh, g_xh);
    cudaGetSymbolAddress((void**)&t512h, g_t512h);
    cudaGetSymbolAddress((void**)&h1h, g_h1h);
    cudaGetSymbolAddress((void**)&wsain, g_wsain);
    cudaGetSymbolAddress((void**)&wsaout, g_wsaout);
    cudaGetSymbolAddress((void**)&wff1, g_wff1);
    cudaGetSymbolAddress((void**)&wff2, g_wff2);
    cudaGetSymbolAddress((void**)&wout, g_wout);

    cudaFuncSetAttribute(gemm_hmma, cudaFuncAttributeMaxDynamicSharedMemorySize, SMEM_DYN);

    auto conv = [&](const float* src, __half* dst, size_t nelem) {
        int n4 = (int)(nelem / 4);
        convB_kernel<<<(n4 + 255) / 256, 256>>>(src, dst, n4);
    };
    auto gemm = [&](const __half* Aw, const __half* Bw, const float* bias,
                    float* C, __half* Ch, int M, int N, int K, int relu) {
        gemm_hmma<<<dim3(M / BM, N / BN), 512, SMEM_DYN>>>(Aw, Bw, bias, C, Ch, M, N, K, relu);
    };

    // bulk weight conversion (once per launch, big coalesced kernels)
    conv(sa_in_w,  wsain,  (size_t)NLAYER * 3 * EDIM * EDIM);
    conv(sa_out_w, wsaout, (size_t)NLAYER * EDIM * EDIM);
    conv(ff1_w,    wff1,   (size_t)NLAYER * FFD * EDIM);
    conv(ff2_w,    wff2,   (size_t)NLAYER * EDIM * FFD);
    conv(out_w,    wout,   (size_t)VOC * EDIM);

    embed_kernel<<<NTOK, 256>>>(caps, W_in, b_in, pos_emb, x, xh);

    for (int i = 0; i < NLAYER; i++) {
        // ---- self attention ----
        gemm(xh, wsain + (size_t)i * 3 * EDIM * EDIM, sa_in_b + (size_t)i * 3 * EDIM,
             qkv, nullptr, NTOK, 3 * EDIM, EDIM, 0);
        attn_kernel<<<32 * NHEAD, 256>>>(qkv, t512h);
        gemm(t512h, wsaout + (size_t)i * EDIM * EDIM, sa_out_b + (size_t)i * EDIM,
             t512, nullptr, NTOK, EDIM, EDIM, 0);
        add_ln_kernel<<<NTOK, 256>>>(x, xh, t512, ln1_w + i * EDIM, ln1_b + i * EDIM, 0);

        // ---- cross attention (constant vector) ----
        ca_const_kernel<<<64, 256>>>(ca_out_w + (size_t)i * EDIM * EDIM,
                                     ca_in_b + (size_t)i * 3 * EDIM + 2 * EDIM,
                                     ca_out_b + (size_t)i * EDIM, cvec);
        add_ln_kernel<<<NTOK, 256>>>(x, xh, cvec, ln2_w + i * EDIM, ln2_b + i * EDIM, 1);

        // ---- FFN ----
        gemm(xh, wff1 + (size_t)i * FFD * EDIM, ff1_b + (size_t)i * FFD,
             nullptr, h1h, NTOK, FFD, EDIM, 1);
        gemm(h1h, wff2 + (size_t)i * EDIM * FFD, ff2_b + (size_t)i * EDIM,
             t512, nullptr, NTOK, EDIM, FFD, 0);
        add_ln_kernel<<<NTOK, 256>>>(x, xh, t512, ln3_w + i * EDIM, ln3_b + i * EDIM, 0);
    }

    // ---- output head ----
    gemm(xh, wout, out_b, (float*)d_out, nullptr, NTOK, VOC, EDIM, 0);
}

// round 5
// speedup vs baseline: 2.5419x; 1.0419x over previous
#include <cuda_runtime.h>
#include <cuda_fp16.h>
#include <cstdint>

#define NTOK 2560
#define EDIM 512
#define NHEAD 8
#define HDIM 64
#define FFD 2048
#define VOC 32000
#define SEQ 80
#define NLAYER 4
#define BK 64

// ---------------- device scratch ----------------
__device__ float g_x[NTOK * EDIM];
__device__ float g_qkv[NTOK * 3 * EDIM];
__device__ float g_t512[NTOK * EDIM];
__device__ float g_c[NLAYER * EDIM];
__device__ __half g_xh[NTOK * EDIM];
__device__ __half g_t512h[NTOK * EDIM];
__device__ __half g_h1h[NTOK * FFD];
__device__ __half g_wsain[NLAYER * 3 * EDIM * EDIM];
__device__ __half g_wsaout[NLAYER * EDIM * EDIM];
__device__ __half g_wff1[NLAYER * FFD * EDIM];
__device__ __half g_wff2[NLAYER * EDIM * FFD];
__device__ __half g_wout[(size_t)VOC * EDIM];

// ---------------- PTX helpers ----------------
__device__ __forceinline__ uint32_t smem_u32(const void* p) {
    uint32_t a;
    asm("{ .reg .u64 t; cvta.to.shared.u64 t, %1; cvt.u32.u64 %0, t; }" : "=r"(a) : "l"(p));
    return a;
}
__device__ __forceinline__ void cp16(uint32_t dst, const void* src) {
    asm volatile("cp.async.cg.shared.global [%0], [%1], 16;\n" :: "r"(dst), "l"(src));
}
__device__ __forceinline__ void cp_commit() { asm volatile("cp.async.commit_group;\n" ::: "memory"); }
template <int N>
__device__ __forceinline__ void cp_wait() { asm volatile("cp.async.wait_group %0;\n" :: "n"(N) : "memory"); }

__device__ __forceinline__ void ldsm4(uint32_t r[4], uint32_t addr) {
    asm volatile("ldmatrix.sync.aligned.m8n8.x4.shared.b16 {%0,%1,%2,%3},[%4];\n"
                 : "=r"(r[0]), "=r"(r[1]), "=r"(r[2]), "=r"(r[3]) : "r"(addr));
}
__device__ __forceinline__ void mma16816(float d[4], const uint32_t a[4], const uint32_t b[2]) {
    asm volatile(
        "mma.sync.aligned.m16n8k16.row.col.f32.f16.f16.f32 "
        "{%0,%1,%2,%3},{%4,%5,%6,%7},{%8,%9},{%0,%1,%2,%3};\n"
        : "+f"(d[0]), "+f"(d[1]), "+f"(d[2]), "+f"(d[3])
        : "r"(a[0]), "r"(a[1]), "r"(a[2]), "r"(a[3]), "r"(b[0]), "r"(b[1]));
}
__device__ __forceinline__ uint32_t swz(uint32_t off) { return off ^ ((off >> 3) & 0x70); }

// ---------------- templated pipelined fp16 HMMA GEMM ----------------
// C[M,N] = A[M,K] @ B[N,K]^T + bias ; fp32 C and/or fp16 Ch output.
// Warp tile: 32 x (NTN*8). CTA tile: (WMG*32) x (WNG*NTN*8). Single sync/stage.
template <int BMt, int BNt, int NWARP, int WMG, int NTN, int NSTG>
__global__ void __launch_bounds__(NWARP * 32) gemm_t(
    const __half* __restrict__ A, const __half* __restrict__ B,
    const float* __restrict__ bias, float* __restrict__ C, __half* __restrict__ Ch,
    int M, int N, int K, int dorelu)
{
    extern __shared__ __align__(16) char sm[];
    constexpr int STB = (BMt + BNt) * 128;
    const int tid = threadIdx.x, lane = tid & 31, warp = tid >> 5;
    const int bm = blockIdx.x * BMt, bn = blockIdx.y * BNt;
    const int wm = (warp % WMG) * 32, wn = (warp / WMG) * (NTN * 8);
    const uint32_t smem0 = smem_u32(sm);

    float acc[2][NTN][4] = {};
    const int S = K / BK;

    auto load_stage = [&](int st, int k0) {
        uint32_t b0 = smem0 + (uint32_t)st * STB;
        constexpr int TOT = (BMt + BNt) * 8;
#pragma unroll
        for (int i = tid; i < TOT; i += NWARP * 32) {
            int r = i >> 3, cb = (i & 7) * 16;
            bool isA = r < BMt;
            int rr = isA ? r : r - BMt;
            uint32_t dst = b0 + (isA ? 0u : (uint32_t)BMt * 128) + swz(rr * 128 + cb);
            const char* p = isA ? (const char*)(A + (size_t)(bm + rr) * K + k0) + cb
                                : (const char*)(B + (size_t)(bn + rr) * K + k0) + cb;
            cp16(dst, p);
        }
    };

#pragma unroll
    for (int s = 0; s < NSTG - 1; s++) {
        if (s < S) load_stage(s, s * BK);
        cp_commit();
    }

    for (int s = 0; s < S; s++) {
        cp_wait<NSTG - 2>();
        __syncthreads();
        if (s + NSTG - 1 < S) load_stage((s + NSTG - 1) % NSTG, (s + NSTG - 1) * BK);
        cp_commit();

        uint32_t b0 = smem0 + (uint32_t)(s % NSTG) * STB;
        uint32_t aA = b0, bB = b0 + (uint32_t)BMt * 128;
#pragma unroll
        for (int kc = 0; kc < 4; kc++) {
            const int kb = kc * 32;
            uint32_t bfr[NTN][2];
            int lrow = lane & 7, seg = lane >> 3;
#pragma unroll
            for (int nt = 0; nt < NTN; nt += 2) {
                uint32_t t4[4];
                ldsm4(t4, bB + swz((wn + (nt + (seg >> 1)) * 8 + lrow) * 128 +
                                   kb + (seg & 1) * 16));
                bfr[nt][0] = t4[0]; bfr[nt][1] = t4[1];
                bfr[nt + 1][0] = t4[2]; bfr[nt + 1][1] = t4[3];
            }
#pragma unroll
            for (int mt = 0; mt < 2; mt++) {
                uint32_t af[4];
                ldsm4(af, aA + swz((wm + mt * 16 + (lane & 15)) * 128 +
                                   kb + (lane >> 4) * 16));
#pragma unroll
                for (int nt = 0; nt < NTN; nt++) mma16816(acc[mt][nt], af, bfr[nt]);
            }
        }
    }

#pragma unroll
    for (int mt = 0; mt < 2; mt++) {
#pragma unroll
        for (int nt = 0; nt < NTN; nt++) {
            int row = bm + wm + mt * 16 + (lane >> 2);
            int col = bn + wn + nt * 8 + (lane & 3) * 2;
            float b0 = bias[col], b1 = bias[col + 1];
            float v0 = acc[mt][nt][0] + b0, v1 = acc[mt][nt][1] + b1;
            float v2 = acc[mt][nt][2] + b0, v3 = acc[mt][nt][3] + b1;
            if (dorelu) {
                v0 = fmaxf(v0, 0.f); v1 = fmaxf(v1, 0.f);
                v2 = fmaxf(v2, 0.f); v3 = fmaxf(v3, 0.f);
            }
            if (C) {
                *(float2*)&C[(size_t)row * N + col] = make_float2(v0, v1);
                *(float2*)&C[(size_t)(row + 8) * N + col] = make_float2(v2, v3);
            }
            if (Ch) {
                *(__half2*)&Ch[(size_t)row * N + col] = __floats2half2_rn(v0, v1);
                *(__half2*)&Ch[(size_t)(row + 8) * N + col] = __floats2half2_rn(v2, v3);
            }
        }
    }
}

// big: 128x256 CTA, 16 warps (4x4), warp 32x64, 3 stages  -> smem 147456
using GemmBigT = void(*)(const __half*, const __half*, const float*, float*, __half*, int, int, int, int);
#define SMEM_BIG (3 * (128 + 256) * 128)
#define SMEM_SMALL (3 * (64 + 128) * 128)

// ---------------- fp32 -> fp16 weights ----------------
__global__ void convB_kernel(const float* __restrict__ s, __half* __restrict__ o, int n4)
{
    int i = blockIdx.x * blockDim.x + threadIdx.x;
    if (i >= n4) return;
    float4 v = ((const float4*)s)[i];
    ((__half2*)o)[2 * i]     = __floats2half2_rn(v.x, v.y);
    ((__half2*)o)[2 * i + 1] = __floats2half2_rn(v.z, v.w);
}

// ---------------- embedding gather (fp32 + fp16) ----------------
__global__ __launch_bounds__(256) void embed_kernel(
    const int* __restrict__ caps, const float* __restrict__ Win,
    const float* __restrict__ bin, const float* __restrict__ pos,
    float* __restrict__ x, __half* __restrict__ xh)
{
    int n = blockIdx.x;
    int tok = caps[n];
    int l = n % SEQ;
#pragma unroll
    for (int e = threadIdx.x; e < EDIM; e += 256) {
        float v = Win[(size_t)e * VOC + tok] + bin[e] + pos[l * EDIM + e];
        x[(size_t)n * EDIM + e] = v;
        xh[(size_t)n * EDIM + e] = __float2half_rn(v);
    }
}

// ---------------- causal self-attention ----------------
__global__ __launch_bounds__(256) void attn_kernel(const float* __restrict__ qkv,
                                                   __half* __restrict__ out)
{
    int b = blockIdx.x >> 3, h = blockIdx.x & 7;
    __shared__ float Kt[80 * 65];
    __shared__ float Vs[80 * 64];
    __shared__ float pr[8 * 80];
    const float* base = qkv + (size_t)b * SEQ * 3 * EDIM;
    for (int i = threadIdx.x; i < 80 * 64; i += 256) {
        int t = i >> 6, d = i & 63;
        Kt[t * 65 + d] = base[t * 1536 + 512 + h * 64 + d];
        Vs[i]          = base[t * 1536 + 1024 + h * 64 + d];
    }
    __syncthreads();
    int warp = threadIdx.x >> 5, lane = threadIdx.x & 31;
    for (int q = warp; q < 80; q += 8) {
        const float* qrow = base + q * 1536 + h * 64;
        int j0 = lane, j1 = lane + 32, j2 = lane + 64;
        const float* k0 = &Kt[j0 * 65];
        const float* k1 = &Kt[(j1 < 80 ? j1 : 0) * 65];
        const float* k2 = &Kt[(j2 < 80 ? j2 : 0) * 65];
        float a0 = 0.f, a1 = 0.f, a2 = 0.f;
#pragma unroll
        for (int kk = 0; kk < 64; kk++) {
            float qv = qrow[kk];
            a0 += qv * k0[kk]; a1 += qv * k1[kk]; a2 += qv * k2[kk];
        }
        float s0 = (j0 <= q) ? a0 * 0.125f : -1e30f;
        float s1 = (j1 <= q) ? a1 * 0.125f : -1e30f;
        float s2 = (j2 <= q) ? a2 * 0.125f : -1e30f;
        float m = fmaxf(fmaxf(s0, s1), s2);
#pragma unroll
        for (int o = 16; o; o >>= 1) m = fmaxf(m, __shfl_xor_sync(0xffffffffu, m, o));
        float p0 = (j0 <= q) ? expf(s0 - m) : 0.f;
        float p1 = (j1 <= q) ? expf(s1 - m) : 0.f;
        float p2 = (j2 <= q) ? expf(s2 - m) : 0.f;
        float sum = p0 + p1 + p2;
#pragma unroll
        for (int o = 16; o; o >>= 1) sum += __shfl_xor_sync(0xffffffffu, sum, o);
        float inv = 1.f / sum;
        pr[warp * 80 + j0] = p0 * inv;
        if (j1 < 80) pr[warp * 80 + j1] = p1 * inv;
        if (j2 < 80) pr[warp * 80 + j2] = p2 * inv;
        __syncwarp();
        float o0 = 0.f, o1 = 0.f;
#pragma unroll 8
        for (int j = 0; j < 80; j++) {   // pr[] is 0 beyond q: fixed-bound, pipelined
            float pv = pr[warp * 80 + j];
            o0 += pv * Vs[j * 64 + lane];
            o1 += pv * Vs[j * 64 + 32 + lane];
        }
        out[(size_t)(b * 80 + q) * EDIM + h * 64 + lane] = __float2half_rn(o0);
        out[(size_t)(b * 80 + q) * EDIM + h * 64 + 32 + lane] = __float2half_rn(o1);
        __syncwarp();
    }
}

// ---------------- block-wide mean/var helper ----------------
__device__ __forceinline__ void blk_stats(float v0, float v1, float* rs, float* rss,
                                          int t, float& mean, float& inv)
{
    float s = v0 + v1, ss = v0 * v0 + v1 * v1;
#pragma unroll
    for (int o = 16; o; o >>= 1) {
        s  += __shfl_xor_sync(0xffffffffu, s, o);
        ss += __shfl_xor_sync(0xffffffffu, ss, o);
    }
    if ((t & 31) == 0) { rs[t >> 5] = s; rss[t >> 5] = ss; }
    __syncthreads();
    float tots = 0.f, totss = 0.f;
#pragma unroll
    for (int i = 0; i < 8; i++) { tots += rs[i]; totss += rss[i]; }
    mean = tots * (1.f / 512.f);
    float var = totss * (1.f / 512.f) - mean * mean;
    inv = rsqrtf(var + 1e-5f);
}

// ---------------- x = LayerNorm(x + add); fp32 + fp16 out ----------------
__global__ __launch_bounds__(256) void add_ln_kernel(
    float* __restrict__ x, __half* __restrict__ xh, const float* __restrict__ add,
    const float* __restrict__ w, const float* __restrict__ b)
{
    int n = blockIdx.x, t = threadIdx.x;
    size_t off = (size_t)n * EDIM;
    __shared__ float rs[8], rss[8];
    float v0 = x[off + t] + add[off + t];
    float v1 = x[off + 256 + t] + add[off + 256 + t];
    float mean, inv;
    blk_stats(v0, v1, rs, rss, t, mean, inv);
    float o0 = (v0 - mean) * inv * w[t] + b[t];
    float o1 = (v1 - mean) * inv * w[256 + t] + b[256 + t];
    x[off + t] = o0;
    x[off + 256 + t] = o1;
    xh[off + t] = __float2half_rn(o0);
    xh[off + 256 + t] = __float2half_rn(o1);
}

// ---------------- fused: y=ln1(x+sa); z=ln2(y+cvec); write z (fp32+fp16) ----------------
__global__ __launch_bounds__(256) void add_ln2_kernel(
    float* __restrict__ x, __half* __restrict__ xh, const float* __restrict__ add,
    const float* __restrict__ cv,
    const float* __restrict__ w1, const float* __restrict__ b1,
    const float* __restrict__ w2, const float* __restrict__ b2)
{
    int n = blockIdx.x, t = threadIdx.x;
    size_t off = (size_t)n * EDIM;
    __shared__ float rs[8], rss[8];
    float v0 = x[off + t] + add[off + t];
    float v1 = x[off + 256 + t] + add[off + 256 + t];
    float mean, inv;
    blk_stats(v0, v1, rs, rss, t, mean, inv);
    float y0 = (v0 - mean) * inv * w1[t] + b1[t] + cv[t];
    float y1 = (v1 - mean) * inv * w1[256 + t] + b1[256 + t] + cv[256 + t];
    __syncthreads();   // rs/rss reuse
    blk_stats(y0, y1, rs, rss, t, mean, inv);
    float o0 = (y0 - mean) * inv * w2[t] + b2[t];
    float o1 = (y1 - mean) * inv * w2[256 + t] + b2[256 + t];
    x[off + t] = o0;
    x[off + 256 + t] = o1;
    xh[off + t] = __float2half_rn(o0);
    xh[off + 256 + t] = __float2half_rn(o1);
}

// ---------------- all-layer cross-attn constant vectors ----------------
__global__ void ca_const_kernel(const float* __restrict__ ow, const float* __restrict__ ib,
                                const float* __restrict__ ob, float* __restrict__ c)
{
    int gw = (blockIdx.x * blockDim.x + threadIdx.x) >> 5;
    int lane = threadIdx.x & 31;
    if (gw >= NLAYER * EDIM) return;
    int layer = gw >> 9, e = gw & 511;
    const float* owl = ow + (size_t)layer * EDIM * EDIM + (size_t)e * EDIM;
    const float* vb = ib + (size_t)layer * 3 * EDIM + 2 * EDIM;
    float s = 0.f;
#pragma unroll
    for (int f = lane; f < EDIM; f += 32) s += owl[f] * vb[f];
#pragma unroll
    for (int o = 16; o; o >>= 1) s += __shfl_xor_sync(0xffffffffu, s, o);
    if (lane == 0) c[gw] = ob[gw] + s;
}

// ---------------- launch ----------------
extern "C" void kernel_launch(void* const* d_in, const int* in_sizes, int n_in,
                              void* d_out, int out_size)
{
    const int*   caps    = (const int*)  d_in[0];
    const float* W_in    = (const float*)d_in[1];
    const float* b_in    = (const float*)d_in[2];
    const float* pos_emb = (const float*)d_in[3];
    const float* sa_in_w  = (const float*)d_in[4];
    const float* sa_in_b  = (const float*)d_in[5];
    const float* sa_out_w = (const float*)d_in[6];
    const float* sa_out_b = (const float*)d_in[7];
    const float* ca_in_b  = (const float*)d_in[9];
    const float* ca_out_w = (const float*)d_in[10];
    const float* ca_out_b = (const float*)d_in[11];
    const float* ff1_w = (const float*)d_in[12];
    const float* ff1_b = (const float*)d_in[13];
    const float* ff2_w = (const float*)d_in[14];
    const float* ff2_b = (const float*)d_in[15];
    const float* ln1_w = (const float*)d_in[16];
    const float* ln1_b = (const float*)d_in[17];
    const float* ln2_w = (const float*)d_in[18];
    const float* ln2_b = (const float*)d_in[19];
    const float* ln3_w = (const float*)d_in[20];
    const float* ln3_b = (const float*)d_in[21];
    const float* out_w = (const float*)d_in[22];
    const float* out_b = (const float*)d_in[23];

    float *x, *qkv, *t512, *cvec;
    __half *xh, *t512h, *h1h, *wsain, *wsaout, *wff1, *wff2, *wout;
    cudaGetSymbolAddress((void**)&x, g_x);
    cudaGetSymbolAddress((void**)&qkv, g_qkv);
    cudaGetSymbolAddress((void**)&t512, g_t512);
    cudaGetSymbolAddress((void**)&cvec, g_c);
    cudaGetSymbolAddress((void**)&xh, g_xh);
    cudaGetSymbolAddress((void**)&t512h, g_t512h);
    cudaGetSymbolAddress((void**)&h1h, g_h1h);
    cudaGetSymbolAddress((void**)&wsain, g_wsain);
    cudaGetSymbolAddress((void**)&wsaout, g_wsaout);
    cudaGetSymbolAddress((void**)&wff1, g_wff1);
    cudaGetSymbolAddress((void**)&wff2, g_wff2);
    cudaGetSymbolAddress((void**)&wout, g_wout);

    auto gemm_big = gemm_t<128, 256, 16, 4, 8, 3>;
    auto gemm_small = gemm_t<64, 128, 8, 2, 4, 3>;
    cudaFuncSetAttribute(gemm_big, cudaFuncAttributeMaxDynamicSharedMemorySize, SMEM_BIG);
    cudaFuncSetAttribute(gemm_small, cudaFuncAttributeMaxDynamicSharedMemorySize, SMEM_SMALL);

    auto conv = [&](const float* src, __half* dst, size_t nelem) {
        int n4 = (int)(nelem / 4);
        convB_kernel<<<(n4 + 255) / 256, 256>>>(src, dst, n4);
    };
    auto gbig = [&](const __half* Aw, const __half* Bw, const float* bias,
                    float* C, __half* Ch, int M, int N, int K, int relu) {
        gemm_big<<<dim3(M / 128, N / 256), 512, SMEM_BIG>>>(Aw, Bw, bias, C, Ch, M, N, K, relu);
    };
    auto gsmall = [&](const __half* Aw, const __half* Bw, const float* bias,
                      float* C, __half* Ch, int M, int N, int K, int relu) {
        gemm_small<<<dim3(M / 64, N / 128), 256, SMEM_SMALL>>>(Aw, Bw, bias, C, Ch, M, N, K, relu);
    };

    conv(sa_in_w,  wsain,  (size_t)NLAYER * 3 * EDIM * EDIM);
    conv(sa_out_w, wsaout, (size_t)NLAYER * EDIM * EDIM);
    conv(ff1_w,    wff1,   (size_t)NLAYER * FFD * EDIM);
    conv(ff2_w,    wff2,   (size_t)NLAYER * EDIM * FFD);
    conv(out_w,    wout,   (size_t)VOC * EDIM);

    ca_const_kernel<<<256, 256>>>(ca_out_w, ca_in_b, ca_out_b, cvec);
    embed_kernel<<<NTOK, 256>>>(caps, W_in, b_in, pos_emb, x, xh);

    for (int i = 0; i < NLAYER; i++) {
        gbig(xh, wsain + (size_t)i * 3 * EDIM * EDIM, sa_in_b + (size_t)i * 3 * EDIM,
             qkv, nullptr, NTOK, 3 * EDIM, EDIM, 0);
        attn_kernel<<<32 * NHEAD, 256>>>(qkv, t512h);
        gsmall(t512h, wsaout + (size_t)i * EDIM * EDIM, sa_out_b + (size_t)i * EDIM,
               t512, nullptr, NTOK, EDIM, EDIM, 0);
        add_ln2_kernel<<<NTOK, 256>>>(x, xh, t512, cvec + i * EDIM,
                                      ln1_w + i * EDIM, ln1_b + i * EDIM,
                                      ln2_w + i * EDIM, ln2_b + i * EDIM);
        gbig(xh, wff1 + (size_t)i * FFD * EDIM, ff1_b + (size_t)i * FFD,
             nullptr, h1h, NTOK, FFD, EDIM, 1);
        gsmall(h1h, wff2 + (size_t)i * EDIM * FFD, ff2_b + (size_t)i * EDIM,
               t512, nullptr, NTOK, EDIM, FFD, 0);
        add_ln_kernel<<<NTOK, 256>>>(x, xh, t512, ln3_w + i * EDIM, ln3_b + i * EDIM);
    }

    gbig(xh, wout, out_b, (float*)d_out, nullptr, NTOK, VOC, EDIM, 0);
}

// round 6
// speedup vs baseline: 2.6063x; 1.0254x over previous
#include <cuda_runtime.h>
#include <cuda_fp16.h>
#include <cstdint>

#define NTOK 2560
#define EDIM 512
#define NHEAD 8
#define HDIM 64
#define FFD 2048
#define VOC 32000
#define SEQ 80
#define NLAYER 4
#define BK 64

// ---------------- device scratch ----------------
__device__ float g_x[NTOK * EDIM];
__device__ float g_qkv[NTOK * 3 * EDIM];
__device__ float g_t512[NTOK * EDIM];
__device__ float g_c[NLAYER * EDIM];
__device__ __half g_xh[NTOK * EDIM];
__device__ __half g_t512h[NTOK * EDIM];
__device__ __half g_h1h[NTOK * FFD];
__device__ __half g_wsain[NLAYER * 3 * EDIM * EDIM];
__device__ __half g_wsaout[NLAYER * EDIM * EDIM];
__device__ __half g_wff1[NLAYER * FFD * EDIM];
__device__ __half g_wff2[NLAYER * EDIM * FFD];
__device__ __half g_wout[(size_t)VOC * EDIM];

// ---------------- PTX helpers ----------------
__device__ __forceinline__ uint32_t smem_u32(const void* p) {
    uint32_t a;
    asm("{ .reg .u64 t; cvta.to.shared.u64 t, %1; cvt.u32.u64 %0, t; }" : "=r"(a) : "l"(p));
    return a;
}
__device__ __forceinline__ void cp16(uint32_t dst, const void* src) {
    asm volatile("cp.async.cg.shared.global [%0], [%1], 16;\n" :: "r"(dst), "l"(src));
}
__device__ __forceinline__ void cp_commit() { asm volatile("cp.async.commit_group;\n" ::: "memory"); }
template <int N>
__device__ __forceinline__ void cp_wait() { asm volatile("cp.async.wait_group %0;\n" :: "n"(N) : "memory"); }

__device__ __forceinline__ void ldsm4(uint32_t r[4], uint32_t addr) {
    asm volatile("ldmatrix.sync.aligned.m8n8.x4.shared.b16 {%0,%1,%2,%3},[%4];\n"
                 : "=r"(r[0]), "=r"(r[1]), "=r"(r[2]), "=r"(r[3]) : "r"(addr));
}
__device__ __forceinline__ void mma16816(float d[4], const uint32_t a[4], const uint32_t b[2]) {
    asm volatile(
        "mma.sync.aligned.m16n8k16.row.col.f32.f16.f16.f32 "
        "{%0,%1,%2,%3},{%4,%5,%6,%7},{%8,%9},{%0,%1,%2,%3};\n"
        : "+f"(d[0]), "+f"(d[1]), "+f"(d[2]), "+f"(d[3])
        : "r"(a[0]), "r"(a[1]), "r"(a[2]), "r"(a[3]), "r"(b[0]), "r"(b[1]));
}
__device__ __forceinline__ uint32_t swz(uint32_t off) { return off ^ ((off >> 3) & 0x70); }

// ---------------- templated pipelined fp16 HMMA GEMM ----------------
template <int BMt, int BNt, int NWARP, int WMG, int NTN, int NSTG>
__global__ void __launch_bounds__(NWARP * 32) gemm_t(
    const __half* __restrict__ A, const __half* __restrict__ B,
    const float* __restrict__ bias, float* __restrict__ C, __half* __restrict__ Ch,
    int M, int N, int K, int dorelu)
{
    extern __shared__ __align__(16) char sm[];
    constexpr int STB = (BMt + BNt) * 128;
    const int tid = threadIdx.x, lane = tid & 31, warp = tid >> 5;
    const int bm = blockIdx.x * BMt, bn = blockIdx.y * BNt;
    const int wm = (warp % WMG) * 32, wn = (warp / WMG) * (NTN * 8);
    const uint32_t smem0 = smem_u32(sm);

    float acc[2][NTN][4] = {};
    const int S = K / BK;

    auto load_stage = [&](int st, int k0) {
        uint32_t b0 = smem0 + (uint32_t)st * STB;
        constexpr int TOT = (BMt + BNt) * 8;
#pragma unroll
        for (int i = tid; i < TOT; i += NWARP * 32) {
            int r = i >> 3, cb = (i & 7) * 16;
            bool isA = r < BMt;
            int rr = isA ? r : r - BMt;
            uint32_t dst = b0 + (isA ? 0u : (uint32_t)BMt * 128) + swz(rr * 128 + cb);
            const char* p = isA ? (const char*)(A + (size_t)(bm + rr) * K + k0) + cb
                                : (const char*)(B + (size_t)(bn + rr) * K + k0) + cb;
            cp16(dst, p);
        }
    };

#pragma unroll
    for (int s = 0; s < NSTG - 1; s++) {
        if (s < S) load_stage(s, s * BK);
        cp_commit();
    }

    for (int s = 0; s < S; s++) {
        cp_wait<NSTG - 2>();
        __syncthreads();
        if (s + NSTG - 1 < S) load_stage((s + NSTG - 1) % NSTG, (s + NSTG - 1) * BK);
        cp_commit();

        uint32_t b0 = smem0 + (uint32_t)(s % NSTG) * STB;
        uint32_t aA = b0, bB = b0 + (uint32_t)BMt * 128;
#pragma unroll
        for (int kc = 0; kc < 4; kc++) {
            const int kb = kc * 32;
            uint32_t bfr[NTN][2];
            int lrow = lane & 7, seg = lane >> 3;
#pragma unroll
            for (int nt = 0; nt < NTN; nt += 2) {
                uint32_t t4[4];
                ldsm4(t4, bB + swz((wn + (nt + (seg >> 1)) * 8 + lrow) * 128 +
                                   kb + (seg & 1) * 16));
                bfr[nt][0] = t4[0]; bfr[nt][1] = t4[1];
                bfr[nt + 1][0] = t4[2]; bfr[nt + 1][1] = t4[3];
            }
#pragma unroll
            for (int mt = 0; mt < 2; mt++) {
                uint32_t af[4];
                ldsm4(af, aA + swz((wm + mt * 16 + (lane & 15)) * 128 +
                                   kb + (lane >> 4) * 16));
#pragma unroll
                for (int nt = 0; nt < NTN; nt++) mma16816(acc[mt][nt], af, bfr[nt]);
            }
        }
    }

#pragma unroll
    for (int mt = 0; mt < 2; mt++) {
#pragma unroll
        for (int nt = 0; nt < NTN; nt++) {
            int row = bm + wm + mt * 16 + (lane >> 2);
            int col = bn + wn + nt * 8 + (lane & 3) * 2;
            float b0 = bias[col], b1 = bias[col + 1];
            float v0 = acc[mt][nt][0] + b0, v1 = acc[mt][nt][1] + b1;
            float v2 = acc[mt][nt][2] + b0, v3 = acc[mt][nt][3] + b1;
            if (dorelu) {
                v0 = fmaxf(v0, 0.f); v1 = fmaxf(v1, 0.f);
                v2 = fmaxf(v2, 0.f); v3 = fmaxf(v3, 0.f);
            }
            if (C) {
                *(float2*)&C[(size_t)row * N + col] = make_float2(v0, v1);
                *(float2*)&C[(size_t)(row + 8) * N + col] = make_float2(v2, v3);
            }
            if (Ch) {
                *(__half2*)&Ch[(size_t)row * N + col] = __floats2half2_rn(v0, v1);
                *(__half2*)&Ch[(size_t)(row + 8) * N + col] = __floats2half2_rn(v2, v3);
            }
        }
    }
}

#define SMEM_BIG (4 * (128 + 256) * 128)
#define SMEM_SMALL (3 * (64 + 128) * 128)

// ---------------- fp32 -> fp16 weights ----------------
__global__ void convB_kernel(const float* __restrict__ s, __half* __restrict__ o, int n4)
{
    int i = blockIdx.x * blockDim.x + threadIdx.x;
    if (i >= n4) return;
    float4 v = ((const float4*)s)[i];
    ((__half2*)o)[2 * i]     = __floats2half2_rn(v.x, v.y);
    ((__half2*)o)[2 * i + 1] = __floats2half2_rn(v.z, v.w);
}

// ---------------- embedding gather (fp32 + fp16) ----------------
__global__ __launch_bounds__(256) void embed_kernel(
    const int* __restrict__ caps, const float* __restrict__ Win,
    const float* __restrict__ bin, const float* __restrict__ pos,
    float* __restrict__ x, __half* __restrict__ xh)
{
    int n = blockIdx.x;
    int tok = caps[n];
    int l = n % SEQ;
#pragma unroll
    for (int e = threadIdx.x; e < EDIM; e += 256) {
        float v = Win[(size_t)e * VOC + tok] + bin[e] + pos[l * EDIM + e];
        x[(size_t)n * EDIM + e] = v;
        xh[(size_t)n * EDIM + e] = __float2half_rn(v);
    }
}

// ---------------- causal self-attention: 2 q-halves per (b,h) ----------------
__global__ __launch_bounds__(256) void attn_kernel(const float* __restrict__ qkv,
                                                   __half* __restrict__ out)
{
    int bh = blockIdx.x >> 1, half = blockIdx.x & 1;
    int b = bh >> 3, h = bh & 7;
    const int kmax = half ? 80 : 40;   // causal: lower half only needs K[0..40)
    __shared__ float Kt[80 * 65];
    __shared__ float Vs[80 * 64];
    __shared__ float pr[8 * 80];
    const float* base = qkv + (size_t)b * SEQ * 3 * EDIM;
    for (int i = threadIdx.x; i < kmax * 64; i += 256) {
        int t = i >> 6, d = i & 63;
        Kt[t * 65 + d] = base[t * 1536 + 512 + h * 64 + d];
        Vs[i]          = base[t * 1536 + 1024 + h * 64 + d];
    }
    __syncthreads();
    int warp = threadIdx.x >> 5, lane = threadIdx.x & 31;
    for (int qi = warp; qi < 40; qi += 8) {
        int q = half * 40 + qi;
        const float* qrow = base + q * 1536 + h * 64;
        int j0 = lane, j1 = lane + 32, j2 = lane + 64;
        const float* k0 = &Kt[j0 * 65];
        const float* k1 = &Kt[(j1 < 80 ? j1 : 0) * 65];
        const float* k2 = &Kt[(j2 < 80 ? j2 : 0) * 65];
        float a0 = 0.f, a1 = 0.f, a2 = 0.f;
#pragma unroll
        for (int kk = 0; kk < 64; kk++) {
            float qv = qrow[kk];
            a0 += qv * k0[kk]; a1 += qv * k1[kk]; a2 += qv * k2[kk];
        }
        float s0 = (j0 <= q) ? a0 * 0.125f : -1e30f;
        float s1 = (j1 <= q) ? a1 * 0.125f : -1e30f;
        float s2 = (j2 <= q) ? a2 * 0.125f : -1e30f;
        float m = fmaxf(fmaxf(s0, s1), s2);
#pragma unroll
        for (int o = 16; o; o >>= 1) m = fmaxf(m, __shfl_xor_sync(0xffffffffu, m, o));
        float p0 = (j0 <= q) ? __expf(s0 - m) : 0.f;
        float p1 = (j1 <= q) ? __expf(s1 - m) : 0.f;
        float p2 = (j2 <= q) ? __expf(s2 - m) : 0.f;
        float sum = p0 + p1 + p2;
#pragma unroll
        for (int o = 16; o; o >>= 1) sum += __shfl_xor_sync(0xffffffffu, sum, o);
        float inv = 1.f / sum;
        pr[warp * 80 + j0] = p0 * inv;
        if (j1 < 80) pr[warp * 80 + j1] = p1 * inv;
        if (j2 < 80) pr[warp * 80 + j2] = p2 * inv;
        __syncwarp();
        float o0 = 0.f, o1 = 0.f;
#pragma unroll 8
        for (int j = 0; j < kmax; j++) {   // pr[] is 0 beyond q
            float pv = pr[warp * 80 + j];
            o0 += pv * Vs[j * 64 + lane];
            o1 += pv * Vs[j * 64 + 32 + lane];
        }
        out[(size_t)(b * 80 + q) * EDIM + h * 64 + lane] = __float2half_rn(o0);
        out[(size_t)(b * 80 + q) * EDIM + h * 64 + 32 + lane] = __float2half_rn(o1);
        __syncwarp();
    }
}

// ---------------- block-wide mean/var helper ----------------
__device__ __forceinline__ void blk_stats(float v0, float v1, float* rs, float* rss,
                                          int t, float& mean, float& inv)
{
    float s = v0 + v1, ss = v0 * v0 + v1 * v1;
#pragma unroll
    for (int o = 16; o; o >>= 1) {
        s  += __shfl_xor_sync(0xffffffffu, s, o);
        ss += __shfl_xor_sync(0xffffffffu, ss, o);
    }
    if ((t & 31) == 0) { rs[t >> 5] = s; rss[t >> 5] = ss; }
    __syncthreads();
    float tots = 0.f, totss = 0.f;
#pragma unroll
    for (int i = 0; i < 8; i++) { tots += rs[i]; totss += rss[i]; }
    mean = tots * (1.f / 512.f);
    float var = totss * (1.f / 512.f) - mean * mean;
    inv = rsqrtf(var + 1e-5f);
}

// ---------------- x = LayerNorm(x + add); fp32 + fp16 out ----------------
__global__ __launch_bounds__(256) void add_ln_kernel(
    float* __restrict__ x, __half* __restrict__ xh, const float* __restrict__ add,
    const float* __restrict__ w, const float* __restrict__ b)
{
    int n = blockIdx.x, t = threadIdx.x;
    size_t off = (size_t)n * EDIM;
    __shared__ float rs[8], rss[8];
    float v0 = x[off + t] + add[off + t];
    float v1 = x[off + 256 + t] + add[off + 256 + t];
    float mean, inv;
    blk_stats(v0, v1, rs, rss, t, mean, inv);
    float o0 = (v0 - mean) * inv * w[t] + b[t];
    float o1 = (v1 - mean) * inv * w[256 + t] + b[256 + t];
    x[off + t] = o0;
    x[off + 256 + t] = o1;
    xh[off + t] = __float2half_rn(o0);
    xh[off + 256 + t] = __float2half_rn(o1);
}

// ---------------- fused ln1 + cvec + ln2 ----------------
__global__ __launch_bounds__(256) void add_ln2_kernel(
    float* __restrict__ x, __half* __restrict__ xh, const float* __restrict__ add,
    const float* __restrict__ cv,
    const float* __restrict__ w1, const float* __restrict__ b1,
    const float* __restrict__ w2, const float* __restrict__ b2)
{
    int n = blockIdx.x, t = threadIdx.x;
    size_t off = (size_t)n * EDIM;
    __shared__ float rs[8], rss[8];
    float v0 = x[off + t] + add[off + t];
    float v1 = x[off + 256 + t] + add[off + 256 + t];
    float mean, inv;
    blk_stats(v0, v1, rs, rss, t, mean, inv);
    float y0 = (v0 - mean) * inv * w1[t] + b1[t] + cv[t];
    float y1 = (v1 - mean) * inv * w1[256 + t] + b1[256 + t] + cv[256 + t];
    __syncthreads();
    blk_stats(y0, y1, rs, rss, t, mean, inv);
    float o0 = (y0 - mean) * inv * w2[t] + b2[t];
    float o1 = (y1 - mean) * inv * w2[256 + t] + b2[256 + t];
    x[off + t] = o0;
    x[off + 256 + t] = o1;
    xh[off + t] = __float2half_rn(o0);
    xh[off + 256 + t] = __float2half_rn(o1);
}

// ---------------- all-layer cross-attn constant vectors ----------------
__global__ void ca_const_kernel(const float* __restrict__ ow, const float* __restrict__ ib,
                                const float* __restrict__ ob, float* __restrict__ c)
{
    int gw = (blockIdx.x * blockDim.x + threadIdx.x) >> 5;
    int lane = threadIdx.x & 31;
    if (gw >= NLAYER * EDIM) return;
    int layer = gw >> 9, e = gw & 511;
    const float* owl = ow + (size_t)layer * EDIM * EDIM + (size_t)e * EDIM;
    const float* vb = ib + (size_t)layer * 3 * EDIM + 2 * EDIM;
    float s = 0.f;
#pragma unroll
    for (int f = lane; f < EDIM; f += 32) s += owl[f] * vb[f];
#pragma unroll
    for (int o = 16; o; o >>= 1) s += __shfl_xor_sync(0xffffffffu, s, o);
    if (lane == 0) c[gw] = ob[gw] + s;
}

// ---------------- launch ----------------
extern "C" void kernel_launch(void* const* d_in, const int* in_sizes, int n_in,
                              void* d_out, int out_size)
{
    const int*   caps    = (const int*)  d_in[0];
    const float* W_in    = (const float*)d_in[1];
    const float* b_in    = (const float*)d_in[2];
    const float* pos_emb = (const float*)d_in[3];
    const float* sa_in_w  = (const float*)d_in[4];
    const float* sa_in_b  = (const float*)d_in[5];
    const float* sa_out_w = (const float*)d_in[6];
    const float* sa_out_b = (const float*)d_in[7];
    const float* ca_in_b  = (const float*)d_in[9];
    const float* ca_out_w = (const float*)d_in[10];
    const float* ca_out_b = (const float*)d_in[11];
    const float* ff1_w = (const float*)d_in[12];
    const float* ff1_b = (const float*)d_in[13];
    const float* ff2_w = (const float*)d_in[14];
    const float* ff2_b = (const float*)d_in[15];
    const float* ln1_w = (const float*)d_in[16];
    const float* ln1_b = (const float*)d_in[17];
    const float* ln2_w = (const float*)d_in[18];
    const float* ln2_b = (const float*)d_in[19];
    const float* ln3_w = (const float*)d_in[20];
    const float* ln3_b = (const float*)d_in[21];
    const float* out_w = (const float*)d_in[22];
    const float* out_b = (const float*)d_in[23];

    float *x, *qkv, *t512, *cvec;
    __half *xh, *t512h, *h1h, *wsain, *wsaout, *wff1, *wff2, *wout;
    cudaGetSymbolAddress((void**)&x, g_x);
    cudaGetSymbolAddress((void**)&qkv, g_qkv);
    cudaGetSymbolAddress((void**)&t512, g_t512);
    cudaGetSymbolAddress((void**)&cvec, g_c);
    cudaGetSymbolAddress((void**)&xh, g_xh);
    cudaGetSymbolAddress((void**)&t512h, g_t512h);
    cudaGetSymbolAddress((void**)&h1h, g_h1h);
    cudaGetSymbolAddress((void**)&wsain, g_wsain);
    cudaGetSymbolAddress((void**)&wsaout, g_wsaout);
    cudaGetSymbolAddress((void**)&wff1, g_wff1);
    cudaGetSymbolAddress((void**)&wff2, g_wff2);
    cudaGetSymbolAddress((void**)&wout, g_wout);

    auto gemm_big = gemm_t<128, 256, 16, 4, 8, 4>;
    auto gemm_small = gemm_t<64, 128, 8, 2, 4, 3>;
    cudaFuncSetAttribute(gemm_big, cudaFuncAttributeMaxDynamicSharedMemorySize, SMEM_BIG);
    cudaFuncSetAttribute(gemm_small, cudaFuncAttributeMaxDynamicSharedMemorySize, SMEM_SMALL);

    auto conv = [&](const float* src, __half* dst, size_t nelem) {
        int n4 = (int)(nelem / 4);
        convB_kernel<<<(n4 + 255) / 256, 256>>>(src, dst, n4);
    };
    auto gbig = [&](const __half* Aw, const __half* Bw, const float* bias,
                    float* C, __half* Ch, int M, int N, int K, int relu) {
        gemm_big<<<dim3(M / 128, N / 256), 512, SMEM_BIG>>>(Aw, Bw, bias, C, Ch, M, N, K, relu);
    };
    auto gsmall = [&](const __half* Aw, const __half* Bw, const float* bias,
                      float* C, __half* Ch, int M, int N, int K, int relu) {
        gemm_small<<<dim3(M / 64, N / 128), 256, SMEM_SMALL>>>(Aw, Bw, bias, C, Ch, M, N, K, relu);
    };

    // launches 0-4: convs + embed ordered so launch #5 = big GEMM (ncu -s 5 -c 1 target)
    conv(sa_in_w,  wsain,  (size_t)NLAYER * 3 * EDIM * EDIM);   // 0
    embed_kernel<<<NTOK, 256>>>(caps, W_in, b_in, pos_emb, x, xh); // 1
    conv(sa_out_w, wsaout, (size_t)NLAYER * EDIM * EDIM);       // 2
    conv(ff1_w,    wff1,   (size_t)NLAYER * FFD * EDIM);        // 3
    conv(ff2_w,    wff2,   (size_t)NLAYER * EDIM * FFD);        // 4

    for (int i = 0; i < NLAYER; i++) {
        gbig(xh, wsain + (size_t)i * 3 * EDIM * EDIM, sa_in_b + (size_t)i * 3 * EDIM,
             qkv, nullptr, NTOK, 3 * EDIM, EDIM, 0);            // 5 on i==0
        if (i == 0)
            ca_const_kernel<<<256, 256>>>(ca_out_w, ca_in_b, ca_out_b, cvec);
        attn_kernel<<<32 * NHEAD * 2, 256>>>(qkv, t512h);
        gsmall(t512h, wsaout + (size_t)i * EDIM * EDIM, sa_out_b + (size_t)i * EDIM,
               t512, nullptr, NTOK, EDIM, EDIM, 0);
        add_ln2_kernel<<<NTOK, 256>>>(x, xh, t512, cvec + i * EDIM,
                                      ln1_w + i * EDIM, ln1_b + i * EDIM,
                                      ln2_w + i * EDIM, ln2_b + i * EDIM);
        gbig(xh, wff1 + (size_t)i * FFD * EDIM, ff1_b + (size_t)i * FFD,
             nullptr, h1h, NTOK, FFD, EDIM, 1);
        gsmall(h1h, wff2 + (size_t)i * EDIM * FFD, ff2_b + (size_t)i * EDIM,
               t512, nullptr, NTOK, EDIM, FFD, 0);
        add_ln_kernel<<<NTOK, 256>>>(x, xh, t512, ln3_w + i * EDIM, ln3_b + i * EDIM);
    }

    conv(out_w, wout, (size_t)VOC * EDIM);
    gbig(xh, wout, out_b, (float*)d_out, nullptr, NTOK, VOC, EDIM, 0);
}

// round 7
// speedup vs baseline: 2.8790x; 1.1046x over previous
#include <cuda_runtime.h>
#include <cuda_fp16.h>
#include <cstdint>

#define NTOK 2560
#define EDIM 512
#define NHEAD 8
#define HDIM 64
#define FFD 2048
#define VOC 32000
#define SEQ 80
#define NLAYER 4
#define BK 64

// ---------------- device scratch ----------------
__device__ float g_x[NTOK * EDIM];
__device__ float g_qkv[NTOK * 3 * EDIM];
__device__ float g_t512[3 * NTOK * EDIM];   // split-K partial outputs
__device__ float g_c[NLAYER * EDIM];
__device__ __half g_xh[NTOK * EDIM];
__device__ __half g_t512h[NTOK * EDIM];
__device__ __half g_h1h[NTOK * FFD];
__device__ __half g_wsain[NLAYER * 3 * EDIM * EDIM];
__device__ __half g_wsaout[NLAYER * EDIM * EDIM];
__device__ __half g_wff1[NLAYER * FFD * EDIM];
__device__ __half g_wff2[NLAYER * EDIM * FFD];
__device__ __half g_wout[(size_t)VOC * EDIM];

// ---------------- PTX helpers ----------------
__device__ __forceinline__ uint32_t smem_u32(const void* p) {
    uint32_t a;
    asm("{ .reg .u64 t; cvta.to.shared.u64 t, %1; cvt.u32.u64 %0, t; }" : "=r"(a) : "l"(p));
    return a;
}
__device__ __forceinline__ void cp16(uint32_t dst, const void* src) {
    asm volatile("cp.async.cg.shared.global [%0], [%1], 16;\n" :: "r"(dst), "l"(src));
}
__device__ __forceinline__ void cp_commit() { asm volatile("cp.async.commit_group;\n" ::: "memory"); }
template <int N>
__device__ __forceinline__ void cp_wait() { asm volatile("cp.async.wait_group %0;\n" :: "n"(N) : "memory"); }

__device__ __forceinline__ void ldsm4(uint32_t r[4], uint32_t addr) {
    asm volatile("ldmatrix.sync.aligned.m8n8.x4.shared.b16 {%0,%1,%2,%3},[%4];\n"
                 : "=r"(r[0]), "=r"(r[1]), "=r"(r[2]), "=r"(r[3]) : "r"(addr));
}
__device__ __forceinline__ void mma16816(float d[4], const uint32_t a[4], const uint32_t b[2]) {
    asm volatile(
        "mma.sync.aligned.m16n8k16.row.col.f32.f16.f16.f32 "
        "{%0,%1,%2,%3},{%4,%5,%6,%7},{%8,%9},{%0,%1,%2,%3};\n"
        : "+f"(d[0]), "+f"(d[1]), "+f"(d[2]), "+f"(d[3])
        : "r"(a[0]), "r"(a[1]), "r"(a[2]), "r"(a[3]), "r"(b[0]), "r"(b[1]));
}
__device__ __forceinline__ uint32_t swz(uint32_t off) { return off ^ ((off >> 3) & 0x70); }

// ---------------- pipelined fp16 HMMA GEMM, 128x128 CTA, split-K via blockIdx.z ----
// C[M,N] (+= over z parts written to C + z*csplit) = A[M,K] @ B[N,K]^T (+ bias on z==0)
#define BMt 128
#define BNt 128
#define NTN 8
#define NSTG 3
#define STB ((BMt + BNt) * 128)
#define SMEM_G (NSTG * STB)

__global__ void __launch_bounds__(256, 2) gemm_k(
    const __half* __restrict__ A, const __half* __restrict__ B,
    const float* __restrict__ bias, float* __restrict__ C, __half* __restrict__ Ch,
    int M, int N, int ldk, int ksp, int K, size_t csplit, int dorelu)
{
    extern __shared__ __align__(16) char sm[];
    const int tid = threadIdx.x, lane = tid & 31, warp = tid >> 5;
    const int bm = blockIdx.x * BMt, bn = blockIdx.y * BNt;
    const int z = blockIdx.z;
    const int k0 = z * ksp;
    const int klen = min(ksp, K - k0);
    const int S = klen / BK;
    const int wm = (warp & 3) * 32, wn = (warp >> 2) * (NTN * 8);
    const uint32_t smem0 = smem_u32(sm);

    float acc[2][NTN][4] = {};

    auto load_stage = [&](int st, int kabs) {
        uint32_t b0 = smem0 + (uint32_t)st * STB;
#pragma unroll
        for (int i = tid; i < (BMt + BNt) * 8; i += 256) {
            int r = i >> 3, cb = (i & 7) * 16;
            bool isA = r < BMt;
            int rr = isA ? r : r - BMt;
            uint32_t dst = b0 + (isA ? 0u : (uint32_t)BMt * 128) + swz(rr * 128 + cb);
            const char* p = isA ? (const char*)(A + (size_t)(bm + rr) * ldk + kabs) + cb
                                : (const char*)(B + (size_t)(bn + rr) * ldk + kabs) + cb;
            cp16(dst, p);
        }
    };

#pragma unroll
    for (int s = 0; s < NSTG - 1; s++) {
        if (s < S) load_stage(s, k0 + s * BK);
        cp_commit();
    }

    for (int s = 0; s < S; s++) {
        cp_wait<NSTG - 2>();
        __syncthreads();
        if (s + NSTG - 1 < S) load_stage((s + NSTG - 1) % NSTG, k0 + (s + NSTG - 1) * BK);
        cp_commit();

        uint32_t b0 = smem0 + (uint32_t)(s % NSTG) * STB;
        uint32_t aA = b0, bB = b0 + (uint32_t)BMt * 128;
#pragma unroll
        for (int kc = 0; kc < 4; kc++) {
            const int kb = kc * 32;
            uint32_t bfr[NTN][2];
            int lrow = lane & 7, seg = lane >> 3;
#pragma unroll
            for (int nt = 0; nt < NTN; nt += 2) {
                uint32_t t4[4];
                ldsm4(t4, bB + swz((wn + (nt + (seg >> 1)) * 8 + lrow) * 128 +
                                   kb + (seg & 1) * 16));
                bfr[nt][0] = t4[0]; bfr[nt][1] = t4[1];
                bfr[nt + 1][0] = t4[2]; bfr[nt + 1][1] = t4[3];
            }
#pragma unroll
            for (int mt = 0; mt < 2; mt++) {
                uint32_t af[4];
                ldsm4(af, aA + swz((wm + mt * 16 + (lane & 15)) * 128 +
                                   kb + (lane >> 4) * 16));
#pragma unroll
                for (int nt = 0; nt < NTN; nt++) mma16816(acc[mt][nt], af, bfr[nt]);
            }
        }
    }

    float* Cz = C ? C + (size_t)z * csplit : nullptr;
#pragma unroll
    for (int mt = 0; mt < 2; mt++) {
#pragma unroll
        for (int nt = 0; nt < NTN; nt++) {
            int row = bm + wm + mt * 16 + (lane >> 2);
            int col = bn + wn + nt * 8 + (lane & 3) * 2;
            float b0 = (z == 0) ? bias[col] : 0.f;
            float b1 = (z == 0) ? bias[col + 1] : 0.f;
            float v0 = acc[mt][nt][0] + b0, v1 = acc[mt][nt][1] + b1;
            float v2 = acc[mt][nt][2] + b0, v3 = acc[mt][nt][3] + b1;
            if (dorelu) {
                v0 = fmaxf(v0, 0.f); v1 = fmaxf(v1, 0.f);
                v2 = fmaxf(v2, 0.f); v3 = fmaxf(v3, 0.f);
            }
            if (Cz) {
                *(float2*)&Cz[(size_t)row * N + col] = make_float2(v0, v1);
                *(float2*)&Cz[(size_t)(row + 8) * N + col] = make_float2(v2, v3);
            }
            if (Ch) {
                *(__half2*)&Ch[(size_t)row * N + col] = __floats2half2_rn(v0, v1);
                *(__half2*)&Ch[(size_t)(row + 8) * N + col] = __floats2half2_rn(v2, v3);
            }
        }
    }
}

// ---------------- fp32 -> fp16 weights ----------------
__global__ void convB_kernel(const float* __restrict__ s, __half* __restrict__ o, int n4)
{
    int i = blockIdx.x * blockDim.x + threadIdx.x;
    if (i >= n4) return;
    float4 v = ((const float4*)s)[i];
    ((__half2*)o)[2 * i]     = __floats2half2_rn(v.x, v.y);
    ((__half2*)o)[2 * i + 1] = __floats2half2_rn(v.z, v.w);
}

// ---------------- embedding gather ----------------
__global__ __launch_bounds__(256) void embed_kernel(
    const int* __restrict__ caps, const float* __restrict__ Win,
    const float* __restrict__ bin, const float* __restrict__ pos,
    float* __restrict__ x, __half* __restrict__ xh)
{
    int n = blockIdx.x;
    int tok = caps[n];
    int l = n % SEQ;
#pragma unroll
    for (int e = threadIdx.x; e < EDIM; e += 256) {
        float v = Win[(size_t)e * VOC + tok] + bin[e] + pos[l * EDIM + e];
        x[(size_t)n * EDIM + e] = v;
        xh[(size_t)n * EDIM + e] = __float2half_rn(v);
    }
}

// ---------------- causal self-attention: 2 q-halves per (b,h) ----------------
__global__ __launch_bounds__(256) void attn_kernel(const float* __restrict__ qkv,
                                                   __half* __restrict__ out)
{
    int bh = blockIdx.x >> 1, half = blockIdx.x & 1;
    int b = bh >> 3, h = bh & 7;
    const int kmax = half ? 80 : 40;
    __shared__ float Kt[80 * 65];
    __shared__ float Vs[80 * 64];
    __shared__ float pr[8 * 80];
    const float* base = qkv + (size_t)b * SEQ * 3 * EDIM;
    for (int i = threadIdx.x; i < kmax * 64; i += 256) {
        int t = i >> 6, d = i & 63;
        Kt[t * 65 + d] = base[t * 1536 + 512 + h * 64 + d];
        Vs[i]          = base[t * 1536 + 1024 + h * 64 + d];
    }
    __syncthreads();
    int warp = threadIdx.x >> 5, lane = threadIdx.x & 31;
    for (int qi = warp; qi < 40; qi += 8) {
        int q = half * 40 + qi;
        const float* qrow = base + q * 1536 + h * 64;
        int j0 = lane, j1 = lane + 32, j2 = lane + 64;
        const float* k0 = &Kt[j0 * 65];
        const float* k1 = &Kt[(j1 < 80 ? j1 : 0) * 65];
        const float* k2 = &Kt[(j2 < 80 ? j2 : 0) * 65];
        float a0 = 0.f, a1 = 0.f, a2 = 0.f;
#pragma unroll
        for (int kk = 0; kk < 64; kk++) {
            float qv = qrow[kk];
            a0 += qv * k0[kk]; a1 += qv * k1[kk]; a2 += qv * k2[kk];
        }
        float s0 = (j0 <= q) ? a0 * 0.125f : -1e30f;
        float s1 = (j1 <= q) ? a1 * 0.125f : -1e30f;
        float s2 = (j2 <= q) ? a2 * 0.125f : -1e30f;
        float m = fmaxf(fmaxf(s0, s1), s2);
#pragma unroll
        for (int o = 16; o; o >>= 1) m = fmaxf(m, __shfl_xor_sync(0xffffffffu, m, o));
        float p0 = (j0 <= q) ? __expf(s0 - m) : 0.f;
        float p1 = (j1 <= q) ? __expf(s1 - m) : 0.f;
        float p2 = (j2 <= q) ? __expf(s2 - m) : 0.f;
        float sum = p0 + p1 + p2;
#pragma unroll
        for (int o = 16; o; o >>= 1) sum += __shfl_xor_sync(0xffffffffu, sum, o);
        float inv = 1.f / sum;
        pr[warp * 80 + j0] = p0 * inv;
        if (j1 < 80) pr[warp * 80 + j1] = p1 * inv;
        if (j2 < 80) pr[warp * 80 + j2] = p2 * inv;
        __syncwarp();
        float o0 = 0.f, o1 = 0.f;
#pragma unroll 8
        for (int j = 0; j < kmax; j++) {
            float pv = pr[warp * 80 + j];
            o0 += pv * Vs[j * 64 + lane];
            o1 += pv * Vs[j * 64 + 32 + lane];
        }
        out[(size_t)(b * 80 + q) * EDIM + h * 64 + lane] = __float2half_rn(o0);
        out[(size_t)(b * 80 + q) * EDIM + h * 64 + 32 + lane] = __float2half_rn(o1);
        __syncwarp();
    }
}

// ---------------- block-wide mean/var helper ----------------
__device__ __forceinline__ void blk_stats(float v0, float v1, float* rs, float* rss,
                                          int t, float& mean, float& inv)
{
    float s = v0 + v1, ss = v0 * v0 + v1 * v1;
#pragma unroll
    for (int o = 16; o; o >>= 1) {
        s  += __shfl_xor_sync(0xffffffffu, s, o);
        ss += __shfl_xor_sync(0xffffffffu, ss, o);
    }
    if ((t & 31) == 0) { rs[t >> 5] = s; rss[t >> 5] = ss; }
    __syncthreads();
    float tots = 0.f, totss = 0.f;
#pragma unroll
    for (int i = 0; i < 8; i++) { tots += rs[i]; totss += rss[i]; }
    mean = tots * (1.f / 512.f);
    float var = totss * (1.f / 512.f) - mean * mean;
    inv = rsqrtf(var + 1e-5f);
}

// ---------------- x = LayerNorm(x + a0+a1+a2); fp32 + fp16 out ----------------
__global__ __launch_bounds__(256) void add_ln_kernel(
    float* __restrict__ x, __half* __restrict__ xh, const float* __restrict__ add,
    const float* __restrict__ w, const float* __restrict__ b)
{
    int n = blockIdx.x, t = threadIdx.x;
    size_t off = (size_t)n * EDIM;
    __shared__ float rs[8], rss[8];
    float v0 = x[off + t]       + add[off + t]       + add[NTOK * EDIM + off + t]
             + add[2 * NTOK * EDIM + off + t];
    float v1 = x[off + 256 + t] + add[off + 256 + t] + add[NTOK * EDIM + off + 256 + t]
             + add[2 * NTOK * EDIM + off + 256 + t];
    float mean, inv;
    blk_stats(v0, v1, rs, rss, t, mean, inv);
    float o0 = (v0 - mean) * inv * w[t] + b[t];
    float o1 = (v1 - mean) * inv * w[256 + t] + b[256 + t];
    x[off + t] = o0;
    x[off + 256 + t] = o1;
    xh[off + t] = __float2half_rn(o0);
    xh[off + 256 + t] = __float2half_rn(o1);
}

// ---------------- fused ln1(x + 3-part sa) + cvec + ln2 ----------------
__global__ __launch_bounds__(256) void add_ln2_kernel(
    float* __restrict__ x, __half* __restrict__ xh, const float* __restrict__ add,
    const float* __restrict__ cv,
    const float* __restrict__ w1, const float* __restrict__ b1,
    const float* __restrict__ w2, const float* __restrict__ b2)
{
    int n = blockIdx.x, t = threadIdx.x;
    size_t off = (size_t)n * EDIM;
    __shared__ float rs[8], rss[8];
    float v0 = x[off + t]       + add[off + t]       + add[NTOK * EDIM + off + t]
             + add[2 * NTOK * EDIM + off + t];
    float v1 = x[off + 256 + t] + add[off + 256 + t] + add[NTOK * EDIM + off + 256 + t]
             + add[2 * NTOK * EDIM + off + 256 + t];
    float mean, inv;
    blk_stats(v0, v1, rs, rss, t, mean, inv);
    float y0 = (v0 - mean) * inv * w1[t] + b1[t] + cv[t];
    float y1 = (v1 - mean) * inv * w1[256 + t] + b1[256 + t] + cv[256 + t];
    __syncthreads();
    blk_stats(y0, y1, rs, rss, t, mean, inv);
    float o0 = (y0 - mean) * inv * w2[t] + b2[t];
    float o1 = (y1 - mean) * inv * w2[256 + t] + b2[256 + t];
    x[off + t] = o0;
    x[off + 256 + t] = o1;
    xh[off + t] = __float2half_rn(o0);
    xh[off + 256 + t] = __float2half_rn(o1);
}

// ---------------- all-layer cross-attn constant vectors ----------------
__global__ void ca_const_kernel(const float* __restrict__ ow, const float* __restrict__ ib,
                                const float* __restrict__ ob, float* __restrict__ c)
{
    int gw = (blockIdx.x * blockDim.x + threadIdx.x) >> 5;
    int lane = threadIdx.x & 31;
    if (gw >= NLAYER * EDIM) return;
    int layer = gw >> 9, e = gw & 511;
    const float* owl = ow + (size_t)layer * EDIM * EDIM + (size_t)e * EDIM;
    const float* vb = ib + (size_t)layer * 3 * EDIM + 2 * EDIM;
    float s = 0.f;
#pragma unroll
    for (int f = lane; f < EDIM; f += 32) s += owl[f] * vb[f];
#pragma unroll
    for (int o = 16; o; o >>= 1) s += __shfl_xor_sync(0xffffffffu, s, o);
    if (lane == 0) c[gw] = ob[gw] + s;
}

// ---------------- launch ----------------
extern "C" void kernel_launch(void* const* d_in, const int* in_sizes, int n_in,
                              void* d_out, int out_size)
{
    const int*   caps    = (const int*)  d_in[0];
    const float* W_in    = (const float*)d_in[1];
    const float* b_in    = (const float*)d_in[2];
    const float* pos_emb = (const float*)d_in[3];
    const float* sa_in_w  = (const float*)d_in[4];
    const float* sa_in_b  = (const float*)d_in[5];
    const float* sa_out_w = (const float*)d_in[6];
    const float* sa_out_b = (const float*)d_in[7];
    const float* ca_in_b  = (const float*)d_in[9];
    const float* ca_out_w = (const float*)d_in[10];
    const float* ca_out_b = (const float*)d_in[11];
    const float* ff1_w = (const float*)d_in[12];
    const float* ff1_b = (const float*)d_in[13];
    const float* ff2_w = (const float*)d_in[14];
    const float* ff2_b = (const float*)d_in[15];
    const float* ln1_w = (const float*)d_in[16];
    const float* ln1_b = (const float*)d_in[17];
    const float* ln2_w = (const float*)d_in[18];
    const float* ln2_b = (const float*)d_in[19];
    const float* ln3_w = (const float*)d_in[20];
    const float* ln3_b = (const float*)d_in[21];
    const float* out_w = (const float*)d_in[22];
    const float* out_b = (const float*)d_in[23];

    float *x, *qkv, *t512, *cvec;
    __half *xh, *t512h, *h1h, *wsain, *wsaout, *wff1, *wff2, *wout;
    cudaGetSymbolAddress((void**)&x, g_x);
    cudaGetSymbolAddress((void**)&qkv, g_qkv);
    cudaGetSymbolAddress((void**)&t512, g_t512);
    cudaGetSymbolAddress((void**)&cvec, g_c);
    cudaGetSymbolAddress((void**)&xh, g_xh);
    cudaGetSymbolAddress((void**)&t512h, g_t512h);
    cudaGetSymbolAddress((void**)&h1h, g_h1h);
    cudaGetSymbolAddress((void**)&wsain, g_wsain);
    cudaGetSymbolAddress((void**)&wsaout, g_wsaout);
    cudaGetSymbolAddress((void**)&wff1, g_wff1);
    cudaGetSymbolAddress((void**)&wff2, g_wff2);
    cudaGetSymbolAddress((void**)&wout, g_wout);

    cudaFuncSetAttribute(gemm_k, cudaFuncAttributeMaxDynamicSharedMemorySize, SMEM_G);

    // fork a side stream for weight conversions (joined before each consumer)
    cudaStream_t s2;
    cudaStreamCreateWithFlags(&s2, cudaStreamNonBlocking);
    cudaEvent_t eFork, eCa, eSaout, eFf1, eFf2, eWout;
    cudaEventCreateWithFlags(&eFork, cudaEventDisableTiming);
    cudaEventCreateWithFlags(&eCa, cudaEventDisableTiming);
    cudaEventCreateWithFlags(&eSaout, cudaEventDisableTiming);
    cudaEventCreateWithFlags(&eFf1, cudaEventDisableTiming);
    cudaEventCreateWithFlags(&eFf2, cudaEventDisableTiming);
    cudaEventCreateWithFlags(&eWout, cudaEventDisableTiming);

    auto convOn = [&](cudaStream_t st, const float* src, __half* dst, size_t nelem) {
        int n4 = (int)(nelem / 4);
        convB_kernel<<<(n4 + 255) / 256, 256, 0, st>>>(src, dst, n4);
    };
    // gemm: grid (M/128, N/128, nz)
    auto gemm = [&](const __half* Aw, const __half* Bw, const float* bias,
                    float* C, __half* Ch, int M, int N, int ldk, int ksp, int K,
                    size_t csplit, int relu) {
        int nz = (K + ksp - 1) / ksp;
        gemm_k<<<dim3(M / 128, N / 128, nz), 256, SMEM_G>>>(
            Aw, Bw, bias, C, Ch, M, N, ldk, ksp, K, csplit, relu);
    };

    cudaEventRecord(eFork, 0);
    cudaStreamWaitEvent(s2, eFork, 0);
    // side stream: ca_const + the 4 late-needed weight conversions
    ca_const_kernel<<<256, 256, 0, s2>>>(ca_out_w, ca_in_b, ca_out_b, cvec);
    cudaEventRecord(eCa, s2);
    convOn(s2, sa_out_w, wsaout, (size_t)NLAYER * EDIM * EDIM);
    cudaEventRecord(eSaout, s2);
    convOn(s2, ff1_w, wff1, (size_t)NLAYER * FFD * EDIM);
    cudaEventRecord(eFf1, s2);
    convOn(s2, ff2_w, wff2, (size_t)NLAYER * EDIM * FFD);
    cudaEventRecord(eFf2, s2);
    convOn(s2, out_w, wout, (size_t)VOC * EDIM);
    cudaEventRecord(eWout, s2);

    // main stream
    convOn(0, sa_in_w, wsain, (size_t)NLAYER * 3 * EDIM * EDIM);
    embed_kernel<<<NTOK, 256>>>(caps, W_in, b_in, pos_emb, x, xh);

    const size_t CS = (size_t)NTOK * EDIM;
    for (int i = 0; i < NLAYER; i++) {
        gemm(xh, wsain + (size_t)i * 3 * EDIM * EDIM, sa_in_b + (size_t)i * 3 * EDIM,
             qkv, nullptr, NTOK, 3 * EDIM, EDIM, EDIM, EDIM, 0, 0);
        attn_kernel<<<32 * NHEAD * 2, 256>>>(qkv, t512h);
        if (i == 0) cudaStreamWaitEvent(0, eSaout, 0);
        gemm(t512h, wsaout + (size_t)i * EDIM * EDIM, sa_out_b + (size_t)i * EDIM,
             t512, nullptr, NTOK, EDIM, EDIM, 192, EDIM, CS, 0);   // split-K 192/192/128
        if (i == 0) cudaStreamWaitEvent(0, eCa, 0);
        add_ln2_kernel<<<NTOK, 256>>>(x, xh, t512, cvec + i * EDIM,
                                      ln1_w + i * EDIM, ln1_b + i * EDIM,
                                      ln2_w + i * EDIM, ln2_b + i * EDIM);
        if (i == 0) cudaStreamWaitEvent(0, eFf1, 0);
        gemm(xh, wff1 + (size_t)i * FFD * EDIM, ff1_b + (size_t)i * FFD,
             nullptr, h1h, NTOK, FFD, EDIM, EDIM, EDIM, 0, 1);
        if (i == 0) cudaStreamWaitEvent(0, eFf2, 0);
        gemm(h1h, wff2 + (size_t)i * EDIM * FFD, ff2_b + (size_t)i * EDIM,
             t512, nullptr, NTOK, EDIM, FFD, 704, FFD, CS, 0);     // split-K 704/704/640
        add_ln_kernel<<<NTOK, 256>>>(x, xh, t512, ln3_w + i * EDIM, ln3_b + i * EDIM);
    }

    cudaStreamWaitEvent(0, eWout, 0);
    gemm(xh, wout, out_b, (float*)d_out, nullptr, NTOK, VOC, EDIM, EDIM, EDIM, 0, 0);
}

// round 8
// speedup vs baseline: 3.0153x; 1.0473x over previous
#include <cuda_runtime.h>
#include <cuda_fp16.h>
#include <cstdint>

#define NTOK 2560
#define EDIM 512
#define NHEAD 8
#define HDIM 64
#define FFD 2048
#define VOC 32000
#define SEQ 80
#define NLAYER 4
#define BK 64

// ---------------- device scratch ----------------
__device__ float g_x[NTOK * EDIM];
__device__ float g_qkv[NTOK * 3 * EDIM];
__device__ float g_t512[3 * NTOK * EDIM];   // split-K partial outputs
__device__ float g_c[NLAYER * EDIM];
__device__ __half g_xh[NTOK * EDIM];
__device__ __half g_t512h[NTOK * EDIM];
__device__ __half g_h1h[NTOK * FFD];
__device__ __half g_wsain[NLAYER * 3 * EDIM * EDIM];
__device__ __half g_wsaout[NLAYER * EDIM * EDIM];
__device__ __half g_wff1[NLAYER * FFD * EDIM];
__device__ __half g_wff2[NLAYER * EDIM * FFD];
__device__ __half g_wout[(size_t)VOC * EDIM];

// ---------------- PTX helpers ----------------
__device__ __forceinline__ uint32_t smem_u32(const void* p) {
    uint32_t a;
    asm("{ .reg .u64 t; cvta.to.shared.u64 t, %1; cvt.u32.u64 %0, t; }" : "=r"(a) : "l"(p));
    return a;
}
__device__ __forceinline__ void cp16(uint32_t dst, const void* src) {
    asm volatile("cp.async.cg.shared.global [%0], [%1], 16;\n" :: "r"(dst), "l"(src));
}
__device__ __forceinline__ void cp_commit() { asm volatile("cp.async.commit_group;\n" ::: "memory"); }
template <int N>
__device__ __forceinline__ void cp_wait() { asm volatile("cp.async.wait_group %0;\n" :: "n"(N) : "memory"); }

__device__ __forceinline__ void ldsm4(uint32_t r[4], uint32_t addr) {
    asm volatile("ldmatrix.sync.aligned.m8n8.x4.shared.b16 {%0,%1,%2,%3},[%4];\n"
                 : "=r"(r[0]), "=r"(r[1]), "=r"(r[2]), "=r"(r[3]) : "r"(addr));
}
__device__ __forceinline__ void mma16816(float d[4], const uint32_t a[4], const uint32_t b[2]) {
    asm volatile(
        "mma.sync.aligned.m16n8k16.row.col.f32.f16.f16.f32 "
        "{%0,%1,%2,%3},{%4,%5,%6,%7},{%8,%9},{%0,%1,%2,%3};\n"
        : "+f"(d[0]), "+f"(d[1]), "+f"(d[2]), "+f"(d[3])
        : "r"(a[0]), "r"(a[1]), "r"(a[2]), "r"(a[3]), "r"(b[0]), "r"(b[1]));
}
__device__ __forceinline__ uint32_t swz(uint32_t off) { return off ^ ((off >> 3) & 0x70); }

// ---------------- pipelined fp16 HMMA GEMM, 128x128 CTA, split-K via blockIdx.z ----
#define BMt 128
#define BNt 128
#define NTN 8
#define NSTG 3
#define STB ((BMt + BNt) * 128)
#define SMEM_G (NSTG * STB)

__global__ void __launch_bounds__(256, 2) gemm_k(
    const __half* __restrict__ A, const __half* __restrict__ B,
    const float* __restrict__ bias, float* __restrict__ C, __half* __restrict__ Ch,
    int M, int N, int ldk, int ksp, int K, size_t csplit, int dorelu)
{
    extern __shared__ __align__(16) char sm[];
    const int tid = threadIdx.x, lane = tid & 31, warp = tid >> 5;
    const int bm = blockIdx.x * BMt, bn = blockIdx.y * BNt;
    const int z = blockIdx.z;
    const int k0 = z * ksp;
    const int klen = min(ksp, K - k0);
    const int S = klen / BK;
    const int wm = (warp & 3) * 32, wn = (warp >> 2) * (NTN * 8);
    const uint32_t smem0 = smem_u32(sm);

    float acc[2][NTN][4] = {};

    auto load_stage = [&](int st, int kabs) {
        uint32_t b0 = smem0 + (uint32_t)st * STB;
#pragma unroll
        for (int i = tid; i < (BMt + BNt) * 8; i += 256) {
            int r = i >> 3, cb = (i & 7) * 16;
            bool isA = r < BMt;
            int rr = isA ? r : r - BMt;
            uint32_t dst = b0 + (isA ? 0u : (uint32_t)BMt * 128) + swz(rr * 128 + cb);
            const char* p = isA ? (const char*)(A + (size_t)(bm + rr) * ldk + kabs) + cb
                                : (const char*)(B + (size_t)(bn + rr) * ldk + kabs) + cb;
            cp16(dst, p);
        }
    };

#pragma unroll
    for (int s = 0; s < NSTG - 1; s++) {
        if (s < S) load_stage(s, k0 + s * BK);
        cp_commit();
    }

    for (int s = 0; s < S; s++) {
        cp_wait<NSTG - 2>();
        __syncthreads();
        if (s + NSTG - 1 < S) load_stage((s + NSTG - 1) % NSTG, k0 + (s + NSTG - 1) * BK);
        cp_commit();

        uint32_t b0 = smem0 + (uint32_t)(s % NSTG) * STB;
        uint32_t aA = b0, bB = b0 + (uint32_t)BMt * 128;
#pragma unroll
        for (int kc = 0; kc < 4; kc++) {
            const int kb = kc * 32;
            uint32_t bfr[NTN][2];
            int lrow = lane & 7, seg = lane >> 3;
#pragma unroll
            for (int nt = 0; nt < NTN; nt += 2) {
                uint32_t t4[4];
                ldsm4(t4, bB + swz((wn + (nt + (seg >> 1)) * 8 + lrow) * 128 +
                                   kb + (seg & 1) * 16));
                bfr[nt][0] = t4[0]; bfr[nt][1] = t4[1];
                bfr[nt + 1][0] = t4[2]; bfr[nt + 1][1] = t4[3];
            }
#pragma unroll
            for (int mt = 0; mt < 2; mt++) {
                uint32_t af[4];
                ldsm4(af, aA + swz((wm + mt * 16 + (lane & 15)) * 128 +
                                   kb + (lane >> 4) * 16));
#pragma unroll
                for (int nt = 0; nt < NTN; nt++) mma16816(acc[mt][nt], af, bfr[nt]);
            }
        }
    }

    float* Cz = C ? C + (size_t)z * csplit : nullptr;
#pragma unroll
    for (int mt = 0; mt < 2; mt++) {
#pragma unroll
        for (int nt = 0; nt < NTN; nt++) {
            int row = bm + wm + mt * 16 + (lane >> 2);
            int col = bn + wn + nt * 8 + (lane & 3) * 2;
            float b0 = (z == 0) ? bias[col] : 0.f;
            float b1 = (z == 0) ? bias[col + 1] : 0.f;
            float v0 = acc[mt][nt][0] + b0, v1 = acc[mt][nt][1] + b1;
            float v2 = acc[mt][nt][2] + b0, v3 = acc[mt][nt][3] + b1;
            if (dorelu) {
                v0 = fmaxf(v0, 0.f); v1 = fmaxf(v1, 0.f);
                v2 = fmaxf(v2, 0.f); v3 = fmaxf(v3, 0.f);
            }
            if (Cz) {
                *(float2*)&Cz[(size_t)row * N + col] = make_float2(v0, v1);
                *(float2*)&Cz[(size_t)(row + 8) * N + col] = make_float2(v2, v3);
            }
            if (Ch) {
                *(__half2*)&Ch[(size_t)row * N + col] = __floats2half2_rn(v0, v1);
                *(__half2*)&Ch[(size_t)(row + 8) * N + col] = __floats2half2_rn(v2, v3);
            }
        }
    }
}

// ---------------- fp32 -> fp16 weights ----------------
__global__ void convB_kernel(const float* __restrict__ s, __half* __restrict__ o, int n4)
{
    int i = blockIdx.x * blockDim.x + threadIdx.x;
    if (i >= n4) return;
    float4 v = ((const float4*)s)[i];
    ((__half2*)o)[2 * i]     = __floats2half2_rn(v.x, v.y);
    ((__half2*)o)[2 * i + 1] = __floats2half2_rn(v.z, v.w);
}

// ---------------- embedding gather ----------------
__global__ __launch_bounds__(256) void embed_kernel(
    const int* __restrict__ caps, const float* __restrict__ Win,
    const float* __restrict__ bin, const float* __restrict__ pos,
    float* __restrict__ x, __half* __restrict__ xh)
{
    int n = blockIdx.x;
    int tok = caps[n];
    int l = n % SEQ;
#pragma unroll
    for (int e = threadIdx.x; e < EDIM; e += 256) {
        float v = Win[(size_t)e * VOC + tok] + bin[e] + pos[l * EDIM + e];
        x[(size_t)n * EDIM + e] = v;
        xh[(size_t)n * EDIM + e] = __float2half_rn(v);
    }
}

// ---------------- causal self-attention: 2 q-halves per (b,h) ----------------
__global__ __launch_bounds__(256) void attn_kernel(const float* __restrict__ qkv,
                                                   __half* __restrict__ out)
{
    int bh = blockIdx.x >> 1, half = blockIdx.x & 1;
    int b = bh >> 3, h = bh & 7;
    const int kmax = half ? 80 : 40;
    __shared__ float Kt[80 * 65];
    __shared__ float Vs[80 * 64];
    __shared__ float pr[8 * 80];
    const float* base = qkv + (size_t)b * SEQ * 3 * EDIM;
    for (int i = threadIdx.x; i < kmax * 64; i += 256) {
        int t = i >> 6, d = i & 63;
        Kt[t * 65 + d] = base[t * 1536 + 512 + h * 64 + d];
        Vs[i]          = base[t * 1536 + 1024 + h * 64 + d];
    }
    __syncthreads();
    int warp = threadIdx.x >> 5, lane = threadIdx.x & 31;
    for (int qi = warp; qi < 40; qi += 8) {
        int q = half * 40 + qi;
        const float* qrow = base + q * 1536 + h * 64;
        int j0 = lane, j1 = lane + 32, j2 = lane + 64;
        const float* k0 = &Kt[j0 * 65];
        const float* k1 = &Kt[(j1 < 80 ? j1 : 0) * 65];
        const float* k2 = &Kt[(j2 < 80 ? j2 : 0) * 65];
        float a0 = 0.f, a1 = 0.f, a2 = 0.f;
#pragma unroll
        for (int kk = 0; kk < 64; kk++) {
            float qv = qrow[kk];
            a0 += qv * k0[kk]; a1 += qv * k1[kk]; a2 += qv * k2[kk];
        }
        float s0 = (j0 <= q) ? a0 * 0.125f : -1e30f;
        float s1 = (j1 <= q) ? a1 * 0.125f : -1e30f;
        float s2 = (j2 <= q) ? a2 * 0.125f : -1e30f;
        float m = fmaxf(fmaxf(s0, s1), s2);
#pragma unroll
        for (int o = 16; o; o >>= 1) m = fmaxf(m, __shfl_xor_sync(0xffffffffu, m, o));
        float p0 = (j0 <= q) ? __expf(s0 - m) : 0.f;
        float p1 = (j1 <= q) ? __expf(s1 - m) : 0.f;
        float p2 = (j2 <= q) ? __expf(s2 - m) : 0.f;
        float sum = p0 + p1 + p2;
#pragma unroll
        for (int o = 16; o; o >>= 1) sum += __shfl_xor_sync(0xffffffffu, sum, o);
        float inv = 1.f / sum;
        pr[warp * 80 + j0] = p0 * inv;
        if (j1 < 80) pr[warp * 80 + j1] = p1 * inv;
        if (j2 < 80) pr[warp * 80 + j2] = p2 * inv;
        __syncwarp();
        float o0 = 0.f, o1 = 0.f;
#pragma unroll 8
        for (int j = 0; j < kmax; j++) {
            float pv = pr[warp * 80 + j];
            o0 += pv * Vs[j * 64 + lane];
            o1 += pv * Vs[j * 64 + 32 + lane];
        }
        out[(size_t)(b * 80 + q) * EDIM + h * 64 + lane] = __float2half_rn(o0);
        out[(size_t)(b * 80 + q) * EDIM + h * 64 + 32 + lane] = __float2half_rn(o1);
        __syncwarp();
    }
}

// ---------------- per-row stats: 2 rows / 256-thread block, 4 vals/thread ----------
__device__ __forceinline__ float2 row_stats(float v0, float v1, float v2, float v3,
                                            float* rs, float* rss, int tid)
{
    float s = v0 + v1 + v2 + v3;
    float ss = v0 * v0 + v1 * v1 + v2 * v2 + v3 * v3;
#pragma unroll
    for (int o = 16; o; o >>= 1) {
        s  += __shfl_xor_sync(0xffffffffu, s, o);
        ss += __shfl_xor_sync(0xffffffffu, ss, o);
    }
    int wid = tid >> 5;
    if ((tid & 31) == 0) { rs[wid] = s; rss[wid] = ss; }
    __syncthreads();
    int base = (tid >> 7) * 4;
    float tots  = rs[base]  + rs[base + 1]  + rs[base + 2]  + rs[base + 3];
    float totss = rss[base] + rss[base + 1] + rss[base + 2] + rss[base + 3];
    float mean = tots * (1.f / 512.f);
    float var = totss * (1.f / 512.f) - mean * mean;
    return make_float2(mean, rsqrtf(var + 1e-5f));
}
__device__ __forceinline__ void st_half4(__half* p, float o0, float o1, float o2, float o3)
{
    __half2 h01 = __floats2half2_rn(o0, o1), h23 = __floats2half2_rn(o2, o3);
    uint2 u;
    u.x = *(uint32_t*)&h01; u.y = *(uint32_t*)&h23;
    *(uint2*)p = u;
}

// ---------------- x = LN(x + a0+a1+a2); vectorized, 2 rows/block ----------------
__global__ __launch_bounds__(256) void add_ln_kernel(
    float* __restrict__ x, __half* __restrict__ xh, const float* __restrict__ add,
    const float* __restrict__ w, const float* __restrict__ b)
{
    __shared__ float rs[8], rss[8];
    int tid = threadIdx.x, tt = tid & 127;
    const size_t P = (size_t)NTOK * EDIM;
    size_t off = (size_t)(blockIdx.x * 2 + (tid >> 7)) * EDIM + tt * 4;
    float4 xv = *(const float4*)&x[off];
    float4 a0 = *(const float4*)&add[off];
    float4 a1 = *(const float4*)&add[P + off];
    float4 a2 = *(const float4*)&add[2 * P + off];
    float v0 = xv.x + a0.x + a1.x + a2.x, v1 = xv.y + a0.y + a1.y + a2.y;
    float v2 = xv.z + a0.z + a1.z + a2.z, v3 = xv.w + a0.w + a1.w + a2.w;
    float2 mi = row_stats(v0, v1, v2, v3, rs, rss, tid);
    int c = tt * 4;
    float4 wv = *(const float4*)&w[c], bv = *(const float4*)&b[c];
    float o0 = (v0 - mi.x) * mi.y * wv.x + bv.x;
    float o1 = (v1 - mi.x) * mi.y * wv.y + bv.y;
    float o2 = (v2 - mi.x) * mi.y * wv.z + bv.z;
    float o3 = (v3 - mi.x) * mi.y * wv.w + bv.w;
    *(float4*)&x[off] = make_float4(o0, o1, o2, o3);
    st_half4(&xh[off], o0, o1, o2, o3);
}

// ---------------- fused ln1(x + 3-part sa) + cvec + ln2; vectorized ----------------
__global__ __launch_bounds__(256) void add_ln2_kernel(
    float* __restrict__ x, __half* __restrict__ xh, const float* __restrict__ add,
    const float* __restrict__ cv,
    const float* __restrict__ w1, const float* __restrict__ b1,
    const float* __restrict__ w2, const float* __restrict__ b2)
{
    __shared__ float rs[8], rss[8];
    int tid = threadIdx.x, tt = tid & 127;
    const size_t P = (size_t)NTOK * EDIM;
    size_t off = (size_t)(blockIdx.x * 2 + (tid >> 7)) * EDIM + tt * 4;
    float4 xv = *(const float4*)&x[off];
    float4 a0 = *(const float4*)&add[off];
    float4 a1 = *(const float4*)&add[P + off];
    float4 a2 = *(const float4*)&add[2 * P + off];
    float v0 = xv.x + a0.x + a1.x + a2.x, v1 = xv.y + a0.y + a1.y + a2.y;
    float v2 = xv.z + a0.z + a1.z + a2.z, v3 = xv.w + a0.w + a1.w + a2.w;
    float2 mi = row_stats(v0, v1, v2, v3, rs, rss, tid);
    int c = tt * 4;
    float4 wv = *(const float4*)&w1[c], bv = *(const float4*)&b1[c];
    float4 cvv = *(const float4*)&cv[c];
    float y0 = (v0 - mi.x) * mi.y * wv.x + bv.x + cvv.x;
    float y1 = (v1 - mi.x) * mi.y * wv.y + bv.y + cvv.y;
    float y2 = (v2 - mi.x) * mi.y * wv.z + bv.z + cvv.z;
    float y3 = (v3 - mi.x) * mi.y * wv.w + bv.w + cvv.w;
    __syncthreads();
    mi = row_stats(y0, y1, y2, y3, rs, rss, tid);
    wv = *(const float4*)&w2[c]; bv = *(const float4*)&b2[c];
    float o0 = (y0 - mi.x) * mi.y * wv.x + bv.x;
    float o1 = (y1 - mi.x) * mi.y * wv.y + bv.y;
    float o2 = (y2 - mi.x) * mi.y * wv.z + bv.z;
    float o3 = (y3 - mi.x) * mi.y * wv.w + bv.w;
    *(float4*)&x[off] = make_float4(o0, o1, o2, o3);
    st_half4(&xh[off], o0, o1, o2, o3);
}

// ---------------- all-layer cross-attn constant vectors ----------------
__global__ void ca_const_kernel(const float* __restrict__ ow, const float* __restrict__ ib,
                                const float* __restrict__ ob, float* __restrict__ c)
{
    int gw = (blockIdx.x * blockDim.x + threadIdx.x) >> 5;
    int lane = threadIdx.x & 31;
    if (gw >= NLAYER * EDIM) return;
    int layer = gw >> 9, e = gw & 511;
    const float* owl = ow + (size_t)layer * EDIM * EDIM + (size_t)e * EDIM;
    const float* vb = ib + (size_t)layer * 3 * EDIM + 2 * EDIM;
    float s = 0.f;
#pragma unroll
    for (int f = lane; f < EDIM; f += 32) s += owl[f] * vb[f];
#pragma unroll
    for (int o = 16; o; o >>= 1) s += __shfl_xor_sync(0xffffffffu, s, o);
    if (lane == 0) c[gw] = ob[gw] + s;
}

// ---------------- launch ----------------
extern "C" void kernel_launch(void* const* d_in, const int* in_sizes, int n_in,
                              void* d_out, int out_size)
{
    const int*   caps    = (const int*)  d_in[0];
    const float* W_in    = (const float*)d_in[1];
    const float* b_in    = (const float*)d_in[2];
    const float* pos_emb = (const float*)d_in[3];
    const float* sa_in_w  = (const float*)d_in[4];
    const float* sa_in_b  = (const float*)d_in[5];
    const float* sa_out_w = (const float*)d_in[6];
    const float* sa_out_b = (const float*)d_in[7];
    const float* ca_in_b  = (const float*)d_in[9];
    const float* ca_out_w = (const float*)d_in[10];
    const float* ca_out_b = (const float*)d_in[11];
    const float* ff1_w = (const float*)d_in[12];
    const float* ff1_b = (const float*)d_in[13];
    const float* ff2_w = (const float*)d_in[14];
    const float* ff2_b = (const float*)d_in[15];
    const float* ln1_w = (const float*)d_in[16];
    const float* ln1_b = (const float*)d_in[17];
    const float* ln2_w = (const float*)d_in[18];
    const float* ln2_b = (const float*)d_in[19];
    const float* ln3_w = (const float*)d_in[20];
    const float* ln3_b = (const float*)d_in[21];
    const float* out_w = (const float*)d_in[22];
    const float* out_b = (const float*)d_in[23];

    float *x, *qkv, *t512, *cvec;
    __half *xh, *t512h, *h1h, *wsain, *wsaout, *wff1, *wff2, *wout;
    cudaGetSymbolAddress((void**)&x, g_x);
    cudaGetSymbolAddress((void**)&qkv, g_qkv);
    cudaGetSymbolAddress((void**)&t512, g_t512);
    cudaGetSymbolAddress((void**)&cvec, g_c);
    cudaGetSymbolAddress((void**)&xh, g_xh);
    cudaGetSymbolAddress((void**)&t512h, g_t512h);
    cudaGetSymbolAddress((void**)&h1h, g_h1h);
    cudaGetSymbolAddress((void**)&wsain, g_wsain);
    cudaGetSymbolAddress((void**)&wsaout, g_wsaout);
    cudaGetSymbolAddress((void**)&wff1, g_wff1);
    cudaGetSymbolAddress((void**)&wff2, g_wff2);
    cudaGetSymbolAddress((void**)&wout, g_wout);

    cudaFuncSetAttribute(gemm_k, cudaFuncAttributeMaxDynamicSharedMemorySize, SMEM_G);

    cudaStream_t s2;
    cudaStreamCreateWithFlags(&s2, cudaStreamNonBlocking);
    cudaEvent_t eFork, eSain, eCa, eSaout, eFf1, eFf2, eWout;
    cudaEventCreateWithFlags(&eFork, cudaEventDisableTiming);
    cudaEventCreateWithFlags(&eSain, cudaEventDisableTiming);
    cudaEventCreateWithFlags(&eCa, cudaEventDisableTiming);
    cudaEventCreateWithFlags(&eSaout, cudaEventDisableTiming);
    cudaEventCreateWithFlags(&eFf1, cudaEventDisableTiming);
    cudaEventCreateWithFlags(&eFf2, cudaEventDisableTiming);
    cudaEventCreateWithFlags(&eWout, cudaEventDisableTiming);

    auto convOn = [&](cudaStream_t st, const float* src, __half* dst, size_t nelem) {
        int n4 = (int)(nelem / 4);
        convB_kernel<<<(n4 + 255) / 256, 256, 0, st>>>(src, dst, n4);
    };
    auto gemm = [&](const __half* Aw, const __half* Bw, const float* bias,
                    float* C, __half* Ch, int M, int N, int ldk, int ksp, int K,
                    size_t csplit, int relu) {
        int nz = (K + ksp - 1) / ksp;
        gemm_k<<<dim3(M / 128, N / 128, nz), 256, SMEM_G>>>(
            Aw, Bw, bias, C, Ch, M, N, ldk, ksp, K, csplit, relu);
    };

    cudaEventRecord(eFork, 0);
    cudaStreamWaitEvent(s2, eFork, 0);

    // launch submission order chosen so index 5 = gemm_k (qkv L0) for ncu -s 5 -c 1
    embed_kernel<<<NTOK, 256>>>(caps, W_in, b_in, pos_emb, x, xh);        // 0 main
    convOn(s2, sa_in_w, wsain, (size_t)NLAYER * 3 * EDIM * EDIM);          // 1 side
    cudaEventRecord(eSain, s2);
    ca_const_kernel<<<256, 256, 0, s2>>>(ca_out_w, ca_in_b, ca_out_b, cvec); // 2 side
    cudaEventRecord(eCa, s2);
    convOn(s2, sa_out_w, wsaout, (size_t)NLAYER * EDIM * EDIM);            // 3 side
    cudaEventRecord(eSaout, s2);
    convOn(s2, ff1_w, wff1, (size_t)NLAYER * FFD * EDIM);                  // 4 side
    cudaEventRecord(eFf1, s2);

    cudaStreamWaitEvent(0, eSain, 0);
    const size_t CS = (size_t)NTOK * EDIM;
    // launch 5: qkv L0 (profiled)
    gemm(xh, wsain, sa_in_b, qkv, nullptr, NTOK, 3 * EDIM, EDIM, EDIM, EDIM, 0, 0);

    convOn(s2, ff2_w, wff2, (size_t)NLAYER * EDIM * FFD);                  // 6 side
    cudaEventRecord(eFf2, s2);
    convOn(s2, out_w, wout, (size_t)VOC * EDIM);                           // 7 side
    cudaEventRecord(eWout, s2);

    for (int i = 0; i < NLAYER; i++) {
        if (i > 0)
            gemm(xh, wsain + (size_t)i * 3 * EDIM * EDIM, sa_in_b + (size_t)i * 3 * EDIM,
                 qkv, nullptr, NTOK, 3 * EDIM, EDIM, EDIM, EDIM, 0, 0);
        attn_kernel<<<32 * NHEAD * 2, 256>>>(qkv, t512h);
        if (i == 0) cudaStreamWaitEvent(0, eSaout, 0);
        gemm(t512h, wsaout + (size_t)i * EDIM * EDIM, sa_out_b + (size_t)i * EDIM,
             t512, nullptr, NTOK, EDIM, EDIM, 192, EDIM, CS, 0);
        if (i == 0) cudaStreamWaitEvent(0, eCa, 0);
        add_ln2_kernel<<<NTOK / 2, 256>>>(x, xh, t512, cvec + i * EDIM,
                                          ln1_w + i * EDIM, ln1_b + i * EDIM,
                                          ln2_w + i * EDIM, ln2_b + i * EDIM);
        if (i == 0) cudaStreamWaitEvent(0, eFf1, 0);
        gemm(xh, wff1 + (size_t)i * FFD * EDIM, ff1_b + (size_t)i * FFD,
             nullptr, h1h, NTOK, FFD, EDIM, EDIM, EDIM, 0, 1);
        if (i == 0) cudaStreamWaitEvent(0, eFf2, 0);
        gemm(h1h, wff2 + (size_t)i * EDIM * FFD, ff2_b + (size_t)i * EDIM,
             t512, nullptr, NTOK, EDIM, FFD, 704, FFD, CS, 0);
        add_ln_kernel<<<NTOK / 2, 256>>>(x, xh, t512, ln3_w + i * EDIM, ln3_b + i * EDIM);
    }

    cudaStreamWaitEvent(0, eWout, 0);
    gemm(xh, wout, out_b, (float*)d_out, nullptr, NTOK, VOC, EDIM, EDIM, EDIM, 0, 0);
}